// round 12
// baseline (speedup 1.0000x reference)
#include <cuda_runtime.h>
#include <cuda_fp16.h>
#include <cstdint>

#define Bsz 2
#define Cch 64
#define Hh  128
#define Ww  128
#define HID 256

// 32 MB scratch for conv3x3(feat, W0) + b0, layout [B][H][W][256]
__device__ float g_z[Bsz * Hh * Ww * HID];
// Pre-packed fp16 weights in mma.sync B-fragment layout: 24 chunks x 16KB
__device__ __half g_wb[3 * 65536];

// ---------------- generic helpers ----------------
__device__ __forceinline__ unsigned long long pack2(float a, float b) {
    unsigned long long r;
    asm("mov.b64 %0, {%1, %2};" : "=l"(r) : "f"(a), "f"(b));
    return r;
}
__device__ __forceinline__ unsigned long long fma2(unsigned long long a,
                                                   unsigned long long b,
                                                   unsigned long long c) {
    unsigned long long d;
    asm("fma.rn.f32x2 %0, %1, %2, %3;" : "=l"(d) : "l"(a), "l"(b), "l"(c));
    return d;
}
__device__ __forceinline__ float2 unpack2(unsigned long long a) {
    float lo, hi;
    asm("mov.b64 {%0, %1}, %2;" : "=f"(lo), "=f"(hi) : "l"(a));
    return make_float2(lo, hi);
}
__device__ __forceinline__ uint32_t s2u(const void* p) {
    uint32_t a;
    asm("{ .reg .u64 t; cvta.to.shared.u64 t, %1; cvt.u32.u64 %0, t; }" : "=r"(a) : "l"(p));
    return a;
}
__device__ __forceinline__ void cpa16(uint32_t d, const void* s) {
    asm volatile("cp.async.ca.shared.global [%0], [%1], 16;" :: "r"(d), "l"(s));
}
__device__ __forceinline__ void cpa_commit() { asm volatile("cp.async.commit_group;"); }
__device__ __forceinline__ void cpa_wait1()  { asm volatile("cp.async.wait_group 1;"); }
__device__ __forceinline__ void cpa_wait0()  { asm volatile("cp.async.wait_group 0;"); }

__device__ __forceinline__ void ldmA(uint32_t& a0, uint32_t& a1, uint32_t& a2,
                                     uint32_t& a3, uint32_t addr) {
    asm volatile("ldmatrix.sync.aligned.m8n8.x4.shared.b16 {%0,%1,%2,%3}, [%4];"
                 : "=r"(a0), "=r"(a1), "=r"(a2), "=r"(a3) : "r"(addr));
}
__device__ __forceinline__ void ldsv2(uint32_t& b0, uint32_t& b1, uint32_t addr) {
    asm volatile("ld.shared.v2.b32 {%0,%1}, [%2];" : "=r"(b0), "=r"(b1) : "r"(addr));
}
__device__ __forceinline__ void mma16816(float& d0, float& d1, float& d2, float& d3,
                                         uint32_t a0, uint32_t a1, uint32_t a2, uint32_t a3,
                                         uint32_t b0, uint32_t b1) {
    asm volatile("mma.sync.aligned.m16n8k16.row.col.f32.f16.f16.f32 "
                 "{%0,%1,%2,%3}, {%4,%5,%6,%7}, {%8,%9}, {%0,%1,%2,%3};"
                 : "+f"(d0), "+f"(d1), "+f"(d2), "+f"(d3)
                 : "r"(a0), "r"(a1), "r"(a2), "r"(a3), "r"(b0), "r"(b1));
}
__device__ __forceinline__ void mma16816h(uint32_t& d0, uint32_t& d1,
                                          uint32_t a0, uint32_t a1, uint32_t a2, uint32_t a3,
                                          uint32_t b0, uint32_t b1) {
    asm volatile("mma.sync.aligned.m16n8k16.row.col.f16.f16.f16.f16 "
                 "{%0,%1}, {%2,%3,%4,%5}, {%6,%7}, {%0,%1};"
                 : "+r"(d0), "+r"(d1)
                 : "r"(a0), "r"(a1), "r"(a2), "r"(a3), "r"(b0), "r"(b1));
}

// ---------------- kernel 0: weight -> fp16 B-fragment layout ----------------
__global__ void prep_kernel(const float* __restrict__ w1,
                            const float* __restrict__ w2,
                            const float* __restrict__ w3)
{
    int t = blockIdx.x * 256 + threadIdx.x;
    if (t >= 3 * 65536) return;
    int l  = t >> 16;
    int kn = t & 65535;
    int k  = kn >> 8;
    int n  = kn & 255;
    const float* w = (l == 0) ? w1 : (l == 1) ? w2 : w3;
    __half o = __float2half_rn(w[k * 256 + n]);
    int ks = k >> 4, kk = k & 15;
    int nt = n >> 3, c = n & 7;
    int lane = c * 4 + ((kk >> 1) & 3);
    int reg  = kk >> 3;
    int half = kk & 1;
    size_t byte = (size_t)l * 131072 + (ks * 32 + nt) * 256
                + lane * 8 + reg * 4 + half * 2;
    g_wb[byte >> 1] = o;
}

// ---------------- kernel 1: z = conv3x3(feat, W0) + b0 ----------------
__device__ __forceinline__ void prefetch12(uint32_t ws_s, const float* wbase, int ch, int tid) {
    const float* g = wbase + (size_t)ch * 3072;
    uint32_t d = ws_s + (uint32_t)((ch % 3) * 12288);
#pragma unroll
    for (int m = 0; m < 3; ++m) {
        int i4 = tid + 256 * m;
        cpa16(d + i4 * 16, g + i4 * 4);
    }
    cpa_commit();
}

__global__ __launch_bounds__(256, 2) void conv_kernel(
    const float* __restrict__ feat, const float* __restrict__ w0,
    const float* __restrict__ b0)
{
    extern __shared__ float sm[];
    float* fs = sm;            // 64 ch x (10x10) patch
    float* ws = sm + 6400;     // 3 x 3072 weight buffers

    int tid = threadIdx.x;
    int blk = blockIdx.x;
    int bb  = blk >> 8;
    int rem = blk & 255;
    int by = rem >> 4, bx = rem & 15;
    int y0 = by * 8 - 1, x0 = bx * 8 - 1;

    uint32_t ws_s = s2u(ws);
    prefetch12(ws_s, w0, 0, tid);
    prefetch12(ws_s, w0, 1, tid);

    for (int idx = tid; idx < 6400; idx += 256) {
        int c  = idx / 100;
        int p  = idx - c * 100;
        int pr = p / 10;
        int pi = pr + y0;
        int pj = (p - pr * 10) + x0;
        float v = 0.f;
        if ((unsigned)pi < Hh && (unsigned)pj < Ww)
            v = feat[((size_t)(bb * Cch + c) * Hh + pi) * Ww + pj];
        fs[idx] = v;
    }

    int r  = tid >> 5;
    int tx = tid & 31;

    unsigned long long acc[8][4];
#pragma unroll
    for (int i = 0; i < 8; ++i)
#pragma unroll
        for (int j = 0; j < 4; ++j) acc[i][j] = 0ull;

    int c_ = 0, ki = 0;
#pragma unroll 1
    for (int ch = 0; ch < 48; ++ch) {
        if (ch + 1 < 48) cpa_wait1(); else cpa_wait0();
        __syncthreads();
        if (ch + 2 < 48) prefetch12(ws_s, w0, ch + 2, tid);
        const float* wsb = ws + (ch % 3) * 3072;
#pragma unroll
        for (int g = 0; g < 4; ++g) {
            const float* ab = fs + c_ * 100 + (r + ki) * 10;
            unsigned long long a2row[10];
#pragma unroll
            for (int t2 = 0; t2 < 10; ++t2) { float a = ab[t2]; a2row[t2] = pack2(a, a); }
#pragma unroll
            for (int kj = 0; kj < 3; ++kj) {
#pragma unroll
                for (int j = 0; j < 4; ++j) {
                    unsigned long long w2 =
                        *(const unsigned long long*)(wsb + (g * 3 + kj) * 256 + 2 * (tx + 32 * j));
#pragma unroll
                    for (int i = 0; i < 8; ++i)
                        acc[i][j] = fma2(a2row[kj + i], w2, acc[i][j]);
                }
            }
            if (++ki == 3) { ki = 0; ++c_; }
        }
    }

    int gy = by * 8 + r;
#pragma unroll
    for (int j = 0; j < 4; ++j) {
        float2 bb2 = ((const float2*)b0)[tx + 32 * j];
#pragma unroll
        for (int i = 0; i < 8; ++i) {
            float2 v = unpack2(acc[i][j]);
            v.x += bb2.x; v.y += bb2.y;
            int gx = bx * 8 + i;
            *(float2*)(g_z + ((size_t)(bb * Hh + gy) * Ww + gx) * HID + 2 * tx + 64 * j) = v;
        }
    }
}

// ---------------- kernel 2: HMMA MLP (layer 0 two-term, layers 1-2 hi-only) ----------------
// grid = 4096, block = 512 (16 warps, 4x4). CTA: 128 rows x 256 cols, K=256.
#define OFF_WBUF 0          // 3 x 16KB weight buffers
#define OFF_ASH  49152      // A hi: 128 x 528B fp16
#define OFF_ASL  116736     // A lo (only consumed by layer 0)
#define OFF_BSM  184320     // b1,b2,b3: 768 f32
#define OFF_W4   187392     // w4: 768 f32
#define OFF_B4   190464
#define OFF_CW   190480     // W0 rows 576..579: 1024 f32
#define SMEM_TOT 194576

__device__ __forceinline__ void prefetch_chunk(uint32_t ws_s, int q, int tid) {
    const char* src = (const char*)g_wb + (size_t)q * 16384;
    uint32_t d = ws_s + (uint32_t)((q % 3) * 16384);
#pragma unroll
    for (int m = 0; m < 2; ++m) {
        int o = (tid + 512 * m) * 16;
        cpa16(d + o, src + o);
    }
    cpa_commit();
}

__global__ __launch_bounds__(512, 1) void mlp_mma_kernel(
    const float* __restrict__ coord, const float* __restrict__ cell,
    const float* __restrict__ w0,
    const float* __restrict__ b1, const float* __restrict__ b2,
    const float* __restrict__ b3,
    const float* __restrict__ w4, const float* __restrict__ b4,
    float* __restrict__ out)
{
    extern __shared__ char smc[];
    float* bsm = (float*)(smc + OFF_BSM);
    float* w4s = (float*)(smc + OFF_W4);
    float* b4s = (float*)(smc + OFF_B4);
    float* cw  = (float*)(smc + OFF_CW);

    int tid  = threadIdx.x;
    int lane = tid & 31;
    int wid  = tid >> 5;
    int wm   = wid >> 2;    // rows wm*32..+31
    int wn   = wid & 3;     // cols wn*64..+63

    uint32_t smem_base = s2u(smc);
    uint32_t ws_s = smem_base + OFF_WBUF;

    prefetch_chunk(ws_s, 0, tid);
    prefetch_chunk(ws_s, 1, tid);

    for (int i = tid; i < 1024; i += 512) cw[i] = w0[576 * 256 + i];
    for (int i = tid; i < 256; i += 512) {
        bsm[i] = b1[i]; bsm[256 + i] = b2[i]; bsm[512 + i] = b3[i];
    }
    for (int i = tid; i < 768; i += 512) w4s[i] = w4[i];
    if (tid < 3) b4s[tid] = b4[tid];

    // ---- geometry: 4 threads per row ----
    int row  = tid >> 2;
    int part = tid & 3;
    int R  = blockIdx.x * 128 + row;
    int gq = R >> 2;
    int s  = R & 3;
    int b  = gq >> 16;

    float c0  = coord[(size_t)gq * 2 + 0];
    float c1  = coord[(size_t)gq * 2 + 1];
    float ce0 = cell[(size_t)gq * 2 + 0] * 128.0f;
    float ce1 = cell[(size_t)gq * 2 + 1] * 128.0f;
    float vx = (s & 2) ? 1.0f : -1.0f;
    float vy = (s & 1) ? 1.0f : -1.0f;

    const float RXY = 1.0f / 128.0f;
    const float LIM = 1.0f - 1e-6f;
    float cx = c0 + vx * RXY; cx = __fadd_rn(cx, 1e-6f);
    cx = fminf(fmaxf(cx, -LIM), LIM);
    float cy = c1 + vy * RXY; cy = __fadd_rn(cy, 1e-6f);
    cy = fminf(fmaxf(cy, -LIM), LIM);
    float fx = __fmul_rn(__fmul_rn(__fadd_rn(cx, 1.0f), 128.0f), 0.5f);
    float fy = __fmul_rn(__fmul_rn(__fadd_rn(cy, 1.0f), 128.0f), 0.5f);
    int ix = (int)fminf(fmaxf(floorf(fx), 0.0f), 127.0f);
    int iy = (int)fminf(fmaxf(floorf(fy), 0.0f), 127.0f);
    float qx = -1.0f + (2.0f * (float)ix + 1.0f) * (1.0f / 128.0f);
    float qy = -1.0f + (2.0f * (float)iy + 1.0f) * (1.0f / 128.0f);
    float rel0 = __fmul_rn(__fsub_rn(c0, qx), 128.0f);
    float rel1 = __fmul_rn(__fsub_rn(c1, qy), 128.0f);
    float area = fabsf(rel0 * rel1) + 1e-9f;

    __syncthreads();   // cw ready

    // ---- layer-0 input: gather z + rank-4 correction + relu -> As hi/lo (fp16) ----
    {
        const float4* zrow = (const float4*)(g_z + ((size_t)((b * Hh + ix) * Ww + iy)) * HID);
        const float4* cwa  = (const float4*)cw;
        char* ph = smc + OFF_ASH + row * 528 + part * 128;
        char* pl = smc + OFF_ASL + row * 528 + part * 128;
#pragma unroll 4
        for (int m = 0; m < 16; ++m) {
            int c4 = part * 16 + m;
            float4 z  = zrow[c4];
            float4 a0 = cwa[c4];
            float4 a1 = cwa[64 + c4];
            float4 a2 = cwa[128 + c4];
            float4 a3 = cwa[192 + c4];
            float v0 = fmaxf(z.x + rel0 * a0.x + rel1 * a1.x + ce0 * a2.x + ce1 * a3.x, 0.f);
            float v1 = fmaxf(z.y + rel0 * a0.y + rel1 * a1.y + ce0 * a2.y + ce1 * a3.y, 0.f);
            float v2 = fmaxf(z.z + rel0 * a0.z + rel1 * a1.z + ce0 * a2.z + ce1 * a3.z, 0.f);
            float v3 = fmaxf(z.w + rel0 * a0.w + rel1 * a1.w + ce0 * a2.w + ce1 * a3.w, 0.f);
            __half h0 = __float2half_rn(v0);
            __half h1 = __float2half_rn(v1);
            __half h2 = __float2half_rn(v2);
            __half h3 = __float2half_rn(v3);
            __half2 hp0 = __halves2half2(h0, h1);
            __half2 hp1 = __halves2half2(h2, h3);
            ((uint32_t*)(ph + m * 8))[0] = *reinterpret_cast<uint32_t*>(&hp0);
            ((uint32_t*)(ph + m * 8))[1] = *reinterpret_cast<uint32_t*>(&hp1);
            __half2 lp0 = __floats2half2_rn(v0 - __half2float(h0), v1 - __half2float(h1));
            __half2 lp1 = __floats2half2_rn(v2 - __half2float(h2), v3 - __half2float(h3));
            ((uint32_t*)(pl + m * 8))[0] = *reinterpret_cast<uint32_t*>(&lp0);
            ((uint32_t*)(pl + m * 8))[1] = *reinterpret_cast<uint32_t*>(&lp1);
        }
    }

    // ---- ldmatrix lane base addresses ----
    int arow = (lane & 7) + ((lane >> 3) & 1) * 8;
    int acol = (lane >> 4) * 16;
    uint32_t ahi0 = smem_base + OFF_ASH + (uint32_t)((wm * 32 + arow) * 528 + acol);
    uint32_t ahi1 = ahi0 + 16 * 528;
    uint32_t alo0 = ahi0 + (OFF_ASL - OFF_ASH);
    uint32_t alo1 = alo0 + 16 * 528;
    uint32_t wbl  = ws_s + lane * 8;

    // ---- layer 0: two-term (hi f32-acc + lo f16-acc) ----
    {
        float acc[2][8][4];
        uint32_t lac[2][8][2];
#pragma unroll
        for (int mt = 0; mt < 2; ++mt)
#pragma unroll
            for (int nt = 0; nt < 8; ++nt) {
#pragma unroll
                for (int i = 0; i < 4; ++i) acc[mt][nt][i] = 0.f;
                lac[mt][nt][0] = 0u; lac[mt][nt][1] = 0u;
            }

#pragma unroll 1
        for (int ch = 0; ch < 8; ++ch) {
            cpa_wait1();
            __syncthreads();
            prefetch_chunk(ws_s, ch + 2, tid);
            uint32_t wb = wbl + (uint32_t)((ch % 3) * 16384);
#pragma unroll
            for (int ki = 0; ki < 2; ++ki) {
                int ks = ch * 2 + ki;
                uint32_t ah0, ah1, ah2, ah3, ag0, ag1, ag2, ag3;
                uint32_t al0, al1, al2, al3, am0, am1, am2, am3;
                ldmA(ah0, ah1, ah2, ah3, ahi0 + ks * 32);
                ldmA(ag0, ag1, ag2, ag3, ahi1 + ks * 32);
                ldmA(al0, al1, al2, al3, alo0 + ks * 32);
                ldmA(am0, am1, am2, am3, alo1 + ks * 32);
                uint32_t base = wb + (uint32_t)(ki * 8192) + (uint32_t)(wn * 2048);
#pragma unroll
                for (int nt = 0; nt < 8; ++nt) {
                    uint32_t bh0, bh1;
                    ldsv2(bh0, bh1, base + nt * 256);
                    mma16816(acc[0][nt][0], acc[0][nt][1], acc[0][nt][2], acc[0][nt][3],
                             ah0, ah1, ah2, ah3, bh0, bh1);
                    mma16816(acc[1][nt][0], acc[1][nt][1], acc[1][nt][2], acc[1][nt][3],
                             ag0, ag1, ag2, ag3, bh0, bh1);
                    mma16816h(lac[0][nt][0], lac[0][nt][1],
                              al0, al1, al2, al3, bh0, bh1);
                    mma16816h(lac[1][nt][0], lac[1][nt][1],
                              am0, am1, am2, am3, bh0, bh1);
                }
            }
        }
        __syncthreads();   // all warps done reading A before epilogue overwrites it

        // epilogue: relu(acc + lo + b1) -> fp16 hi only (layers 1-2 are hi-only)
#pragma unroll
        for (int mt = 0; mt < 2; ++mt) {
            int r0 = wm * 32 + mt * 16 + (lane >> 2);
#pragma unroll
            for (int nt = 0; nt < 8; ++nt) {
                int c = wn * 64 + nt * 8 + (lane & 3) * 2;
                float bb0 = bsm[c];
                float bb1 = bsm[c + 1];
                float2 lo0 = __half22float2(*reinterpret_cast<__half2*>(&lac[mt][nt][0]));
                float2 lo1 = __half22float2(*reinterpret_cast<__half2*>(&lac[mt][nt][1]));
#pragma unroll
                for (int hh = 0; hh < 2; ++hh) {
                    int r = r0 + hh * 8;
                    float lx = hh ? lo1.x : lo0.x;
                    float ly = hh ? lo1.y : lo0.y;
                    float v0 = fmaxf(acc[mt][nt][2 * hh]     + lx + bb0, 0.f);
                    float v1 = fmaxf(acc[mt][nt][2 * hh + 1] + ly + bb1, 0.f);
                    __half2 hp = __floats2half2_rn(v0, v1);
                    *(uint32_t*)(smc + OFF_ASH + r * 528 + c * 2) =
                        *reinterpret_cast<uint32_t*>(&hp);
                }
            }
        }
    }

    // ---- layers 1 and 2: hi-only (light registers) ----
#pragma unroll 1
    for (int l = 1; l < 3; ++l) {
        float acc[2][8][4];
#pragma unroll
        for (int mt = 0; mt < 2; ++mt)
#pragma unroll
            for (int nt = 0; nt < 8; ++nt)
#pragma unroll
                for (int i = 0; i < 4; ++i) acc[mt][nt][i] = 0.f;

#pragma unroll 1
        for (int ch = 0; ch < 8; ++ch) {
            int q = l * 8 + ch;
            if (q + 1 < 24) cpa_wait1(); else cpa_wait0();
            __syncthreads();
            if (q + 2 < 24) prefetch_chunk(ws_s, q + 2, tid);
            uint32_t wb = wbl + (uint32_t)((q % 3) * 16384);
#pragma unroll
            for (int ki = 0; ki < 2; ++ki) {
                int ks = ch * 2 + ki;
                uint32_t ah0, ah1, ah2, ah3, ag0, ag1, ag2, ag3;
                ldmA(ah0, ah1, ah2, ah3, ahi0 + ks * 32);
                ldmA(ag0, ag1, ag2, ag3, ahi1 + ks * 32);
                uint32_t base = wb + (uint32_t)(ki * 8192) + (uint32_t)(wn * 2048);
#pragma unroll
                for (int nt = 0; nt < 8; ++nt) {
                    uint32_t bh0, bh1;
                    ldsv2(bh0, bh1, base + nt * 256);
                    mma16816(acc[0][nt][0], acc[0][nt][1], acc[0][nt][2], acc[0][nt][3],
                             ah0, ah1, ah2, ah3, bh0, bh1);
                    mma16816(acc[1][nt][0], acc[1][nt][1], acc[1][nt][2], acc[1][nt][3],
                             ag0, ag1, ag2, ag3, bh0, bh1);
                }
            }
        }
        __syncthreads();

        if (l < 2) {
            // epilogue: relu(acc + b2) -> fp16 hi
#pragma unroll
            for (int mt = 0; mt < 2; ++mt) {
                int r0 = wm * 32 + mt * 16 + (lane >> 2);
#pragma unroll
                for (int nt = 0; nt < 8; ++nt) {
                    int c = wn * 64 + nt * 8 + (lane & 3) * 2;
                    float bb0 = bsm[l * 256 + c];
                    float bb1 = bsm[l * 256 + c + 1];
#pragma unroll
                    for (int hh = 0; hh < 2; ++hh) {
                        int r = r0 + hh * 8;
                        float v0 = fmaxf(acc[mt][nt][2 * hh]     + bb0, 0.f);
                        float v1 = fmaxf(acc[mt][nt][2 * hh + 1] + bb1, 0.f);
                        __half2 hp = __floats2half2_rn(v0, v1);
                        *(uint32_t*)(smc + OFF_ASH + r * 528 + c * 2) =
                            *reinterpret_cast<uint32_t*>(&hp);
                    }
                }
            }
        } else {
            // final epilogue -> fp32 scratch
            float* As32 = (float*)(smc + OFF_ASH);
#pragma unroll
            for (int mt = 0; mt < 2; ++mt) {
                int r0 = wm * 32 + mt * 16 + (lane >> 2);
#pragma unroll
                for (int nt = 0; nt < 8; ++nt) {
                    int c = wn * 64 + nt * 8 + (lane & 3) * 2;
                    float bb0 = bsm[512 + c];
                    float bb1 = bsm[512 + c + 1];
#pragma unroll
                    for (int hh = 0; hh < 2; ++hh) {
                        int r = r0 + hh * 8;
                        As32[r * 260 + c]     = fmaxf(acc[mt][nt][2 * hh]     + bb0, 0.f);
                        As32[r * 260 + c + 1] = fmaxf(acc[mt][nt][2 * hh + 1] + bb1, 0.f);
                    }
                }
            }
        }
        __syncthreads();
    }

    // ---- head + ensemble ----
    {
        const float* As32 = (const float*)(smc + OFF_ASH);
        const float* arow_p = As32 + row * 260 + part * 64;
        float a0 = 0.f, a1 = 0.f, a2 = 0.f;
#pragma unroll 8
        for (int k = 0; k < 64; ++k) {
            float a = arow_p[k];
            int kg = part * 64 + k;
            a0 += a * w4s[kg * 3 + 0];
            a1 += a * w4s[kg * 3 + 1];
            a2 += a * w4s[kg * 3 + 2];
        }
        a0 += __shfl_xor_sync(0xFFFFFFFFu, a0, 1);
        a0 += __shfl_xor_sync(0xFFFFFFFFu, a0, 2);
        a1 += __shfl_xor_sync(0xFFFFFFFFu, a1, 1);
        a1 += __shfl_xor_sync(0xFFFFFFFFu, a1, 2);
        a2 += __shfl_xor_sync(0xFFFFFFFFu, a2, 1);
        a2 += __shfl_xor_sync(0xFFFFFFFFu, a2, 2);
        a0 += b4s[0]; a1 += b4s[1]; a2 += b4s[2];

        float aswap = __shfl_xor_sync(0xFFFFFFFFu, area, 12);
        float t1 = area + __shfl_xor_sync(0xFFFFFFFFu, area, 4);
        float tot = t1 + __shfl_xor_sync(0xFFFFFFFFu, t1, 8);
        float o0 = a0 * aswap, o1 = a1 * aswap, o2 = a2 * aswap;
        o0 += __shfl_xor_sync(0xFFFFFFFFu, o0, 4);
        o0 += __shfl_xor_sync(0xFFFFFFFFu, o0, 8);
        o1 += __shfl_xor_sync(0xFFFFFFFFu, o1, 4);
        o1 += __shfl_xor_sync(0xFFFFFFFFu, o1, 8);
        o2 += __shfl_xor_sync(0xFFFFFFFFu, o2, 4);
        o2 += __shfl_xor_sync(0xFFFFFFFFu, o2, 8);
        if ((tid & 15) == 0) {
            int gqo = blockIdx.x * 32 + (tid >> 4);
            out[(size_t)gqo * 3 + 0] = o0 / tot;
            out[(size_t)gqo * 3 + 1] = o1 / tot;
            out[(size_t)gqo * 3 + 2] = o2 / tot;
        }
    }
}

extern "C" void kernel_launch(void* const* d_in, const int* in_sizes, int n_in,
                              void* d_out, int out_size)
{
    const float* feat  = (const float*)d_in[0];
    const float* coord = (const float*)d_in[1];
    const float* cell  = (const float*)d_in[2];
    const float* w0 = (const float*)d_in[3];
    const float* b0 = (const float*)d_in[4];
    const float* w1 = (const float*)d_in[5];
    const float* b1 = (const float*)d_in[6];
    const float* w2 = (const float*)d_in[7];
    const float* b2 = (const float*)d_in[8];
    const float* w3 = (const float*)d_in[9];
    const float* b3 = (const float*)d_in[10];
    const float* w4 = (const float*)d_in[11];
    const float* b4 = (const float*)d_in[12];
    float* out = (float*)d_out;

    int conv_smem = (6400 + 9216) * 4;
    cudaFuncSetAttribute((const void*)conv_kernel,
                         cudaFuncAttributeMaxDynamicSharedMemorySize, conv_smem);
    cudaFuncSetAttribute((const void*)mlp_mma_kernel,
                         cudaFuncAttributeMaxDynamicSharedMemorySize, SMEM_TOT);

    prep_kernel<<<768, 256>>>(w1, w2, w3);
    conv_kernel<<<512, 256, conv_smem>>>(feat, w0, b0);
    mlp_mma_kernel<<<4096, 512, SMEM_TOT>>>(coord, cell, w0, b1, b2, b3, w4, b4, out);
}

// round 13
// speedup vs baseline: 1.5787x; 1.5787x over previous
#include <cuda_runtime.h>
#include <cuda_fp16.h>
#include <cstdint>

#define Bsz 2
#define Cch 64
#define Hh  128
#define Ww  128
#define HID 256

// 32 MB scratch for conv3x3(feat, W0) + b0, layout [B][H][W][256]
__device__ float g_z[Bsz * Hh * Ww * HID];
// Pre-packed fp16 weights in mma.sync B-fragment layout: 24 chunks x 16KB
__device__ __half g_wb[3 * 65536];

// ---------------- generic helpers ----------------
__device__ __forceinline__ unsigned long long pack2(float a, float b) {
    unsigned long long r;
    asm("mov.b64 %0, {%1, %2};" : "=l"(r) : "f"(a), "f"(b));
    return r;
}
__device__ __forceinline__ unsigned long long fma2(unsigned long long a,
                                                   unsigned long long b,
                                                   unsigned long long c) {
    unsigned long long d;
    asm("fma.rn.f32x2 %0, %1, %2, %3;" : "=l"(d) : "l"(a), "l"(b), "l"(c));
    return d;
}
__device__ __forceinline__ float2 unpack2(unsigned long long a) {
    float lo, hi;
    asm("mov.b64 {%0, %1}, %2;" : "=f"(lo), "=f"(hi) : "l"(a));
    return make_float2(lo, hi);
}
__device__ __forceinline__ uint32_t s2u(const void* p) {
    uint32_t a;
    asm("{ .reg .u64 t; cvta.to.shared.u64 t, %1; cvt.u32.u64 %0, t; }" : "=r"(a) : "l"(p));
    return a;
}
__device__ __forceinline__ void cpa16(uint32_t d, const void* s) {
    asm volatile("cp.async.ca.shared.global [%0], [%1], 16;" :: "r"(d), "l"(s));
}
__device__ __forceinline__ void cpa_commit() { asm volatile("cp.async.commit_group;"); }
__device__ __forceinline__ void cpa_wait1()  { asm volatile("cp.async.wait_group 1;"); }
__device__ __forceinline__ void cpa_wait0()  { asm volatile("cp.async.wait_group 0;"); }

__device__ __forceinline__ void ldmA(uint32_t& a0, uint32_t& a1, uint32_t& a2,
                                     uint32_t& a3, uint32_t addr) {
    asm volatile("ldmatrix.sync.aligned.m8n8.x4.shared.b16 {%0,%1,%2,%3}, [%4];"
                 : "=r"(a0), "=r"(a1), "=r"(a2), "=r"(a3) : "r"(addr));
}
__device__ __forceinline__ void ldsv2(uint32_t& b0, uint32_t& b1, uint32_t addr) {
    asm volatile("ld.shared.v2.b32 {%0,%1}, [%2];" : "=r"(b0), "=r"(b1) : "r"(addr));
}
__device__ __forceinline__ void mma16816(float& d0, float& d1, float& d2, float& d3,
                                         uint32_t a0, uint32_t a1, uint32_t a2, uint32_t a3,
                                         uint32_t b0, uint32_t b1) {
    asm volatile("mma.sync.aligned.m16n8k16.row.col.f32.f16.f16.f32 "
                 "{%0,%1,%2,%3}, {%4,%5,%6,%7}, {%8,%9}, {%0,%1,%2,%3};"
                 : "+f"(d0), "+f"(d1), "+f"(d2), "+f"(d3)
                 : "r"(a0), "r"(a1), "r"(a2), "r"(a3), "r"(b0), "r"(b1));
}
__device__ __forceinline__ void mma16816h(uint32_t& d0, uint32_t& d1,
                                          uint32_t a0, uint32_t a1, uint32_t a2, uint32_t a3,
                                          uint32_t b0, uint32_t b1) {
    asm volatile("mma.sync.aligned.m16n8k16.row.col.f16.f16.f16.f16 "
                 "{%0,%1}, {%2,%3,%4,%5}, {%6,%7}, {%0,%1};"
                 : "+r"(d0), "+r"(d1)
                 : "r"(a0), "r"(a1), "r"(a2), "r"(a3), "r"(b0), "r"(b1));
}

// ---------------- kernel 0: weight -> fp16 B-fragment layout ----------------
__global__ void prep_kernel(const float* __restrict__ w1,
                            const float* __restrict__ w2,
                            const float* __restrict__ w3)
{
    int t = blockIdx.x * 256 + threadIdx.x;
    if (t >= 3 * 65536) return;
    int l  = t >> 16;
    int kn = t & 65535;
    int k  = kn >> 8;
    int n  = kn & 255;
    const float* w = (l == 0) ? w1 : (l == 1) ? w2 : w3;
    __half o = __float2half_rn(w[k * 256 + n]);
    int ks = k >> 4, kk = k & 15;
    int nt = n >> 3, c = n & 7;
    int lane = c * 4 + ((kk >> 1) & 3);
    int reg  = kk >> 3;
    int half = kk & 1;
    size_t byte = (size_t)l * 131072 + (ks * 32 + nt) * 256
                + lane * 8 + reg * 4 + half * 2;
    g_wb[byte >> 1] = o;
}

// ---------------- kernel 1: z = conv3x3(feat, W0) + b0 ----------------
__device__ __forceinline__ void prefetch12(uint32_t ws_s, const float* wbase, int ch, int tid) {
    const float* g = wbase + (size_t)ch * 3072;
    uint32_t d = ws_s + (uint32_t)((ch % 3) * 12288);
#pragma unroll
    for (int m = 0; m < 3; ++m) {
        int i4 = tid + 256 * m;
        cpa16(d + i4 * 16, g + i4 * 4);
    }
    cpa_commit();
}

__global__ __launch_bounds__(256, 2) void conv_kernel(
    const float* __restrict__ feat, const float* __restrict__ w0,
    const float* __restrict__ b0)
{
    extern __shared__ float sm[];
    float* fs = sm;            // 64 ch x (10x10) patch
    float* ws = sm + 6400;     // 3 x 3072 weight buffers

    int tid = threadIdx.x;
    int blk = blockIdx.x;
    int bb  = blk >> 8;
    int rem = blk & 255;
    int by = rem >> 4, bx = rem & 15;
    int y0 = by * 8 - 1, x0 = bx * 8 - 1;

    uint32_t ws_s = s2u(ws);
    prefetch12(ws_s, w0, 0, tid);
    prefetch12(ws_s, w0, 1, tid);

    for (int idx = tid; idx < 6400; idx += 256) {
        int c  = idx / 100;
        int p  = idx - c * 100;
        int pr = p / 10;
        int pi = pr + y0;
        int pj = (p - pr * 10) + x0;
        float v = 0.f;
        if ((unsigned)pi < Hh && (unsigned)pj < Ww)
            v = feat[((size_t)(bb * Cch + c) * Hh + pi) * Ww + pj];
        fs[idx] = v;
    }

    int r  = tid >> 5;
    int tx = tid & 31;

    unsigned long long acc[8][4];
#pragma unroll
    for (int i = 0; i < 8; ++i)
#pragma unroll
        for (int j = 0; j < 4; ++j) acc[i][j] = 0ull;

    int c_ = 0, ki = 0;
#pragma unroll 1
    for (int ch = 0; ch < 48; ++ch) {
        if (ch + 1 < 48) cpa_wait1(); else cpa_wait0();
        __syncthreads();
        if (ch + 2 < 48) prefetch12(ws_s, w0, ch + 2, tid);
        const float* wsb = ws + (ch % 3) * 3072;
#pragma unroll
        for (int g = 0; g < 4; ++g) {
            const float* ab = fs + c_ * 100 + (r + ki) * 10;
            unsigned long long a2row[10];
#pragma unroll
            for (int t2 = 0; t2 < 10; ++t2) { float a = ab[t2]; a2row[t2] = pack2(a, a); }
#pragma unroll
            for (int kj = 0; kj < 3; ++kj) {
#pragma unroll
                for (int j = 0; j < 4; ++j) {
                    unsigned long long w2 =
                        *(const unsigned long long*)(wsb + (g * 3 + kj) * 256 + 2 * (tx + 32 * j));
#pragma unroll
                    for (int i = 0; i < 8; ++i)
                        acc[i][j] = fma2(a2row[kj + i], w2, acc[i][j]);
                }
            }
            if (++ki == 3) { ki = 0; ++c_; }
        }
    }

    int gy = by * 8 + r;
#pragma unroll
    for (int j = 0; j < 4; ++j) {
        float2 bb2 = ((const float2*)b0)[tx + 32 * j];
#pragma unroll
        for (int i = 0; i < 8; ++i) {
            float2 v = unpack2(acc[i][j]);
            v.x += bb2.x; v.y += bb2.y;
            int gx = bx * 8 + i;
            *(float2*)(g_z + ((size_t)(bb * Hh + gy) * Ww + gx) * HID + 2 * tx + 64 * j) = v;
        }
    }
}

// ---------------- kernel 2: HMMA MLP (layer 0 two-term, layers 1-2 hi-only) ----------------
// grid = 4096, block = 512 (16 warps, 4x4). CTA: 128 rows x 256 cols, K=256.
// STRUCTURE RULE (R10/R12 lesson): each layer is its own straight-line block
// with a single unbranched epilogue — never merge layers into a loop with an
// if-diverging epilogue next to the 64-float accumulator array.
#define OFF_WBUF 0          // 3 x 16KB weight buffers
#define OFF_ASH  49152      // A hi: 128 x 528B fp16
#define OFF_ASL  116736     // A lo (only consumed by layer 0)
#define OFF_BSM  184320     // b1,b2,b3: 768 f32
#define OFF_W4   187392     // w4: 768 f32
#define OFF_B4   190464
#define OFF_CW   190480     // W0 rows 576..579: 1024 f32
#define SMEM_TOT 194576

__device__ __forceinline__ void prefetch_chunk(uint32_t ws_s, int q, int tid) {
    const char* src = (const char*)g_wb + (size_t)q * 16384;
    uint32_t d = ws_s + (uint32_t)((q % 3) * 16384);
#pragma unroll
    for (int m = 0; m < 2; ++m) {
        int o = (tid + 512 * m) * 16;
        cpa16(d + o, src + o);
    }
    cpa_commit();
}

__global__ __launch_bounds__(512, 1) void mlp_mma_kernel(
    const float* __restrict__ coord, const float* __restrict__ cell,
    const float* __restrict__ w0,
    const float* __restrict__ b1, const float* __restrict__ b2,
    const float* __restrict__ b3,
    const float* __restrict__ w4, const float* __restrict__ b4,
    float* __restrict__ out)
{
    extern __shared__ char smc[];
    float* bsm = (float*)(smc + OFF_BSM);
    float* w4s = (float*)(smc + OFF_W4);
    float* b4s = (float*)(smc + OFF_B4);
    float* cw  = (float*)(smc + OFF_CW);

    int tid  = threadIdx.x;
    int lane = tid & 31;
    int wid  = tid >> 5;
    int wm   = wid >> 2;    // rows wm*32..+31
    int wn   = wid & 3;     // cols wn*64..+63

    uint32_t smem_base = s2u(smc);
    uint32_t ws_s = smem_base + OFF_WBUF;

    prefetch_chunk(ws_s, 0, tid);
    prefetch_chunk(ws_s, 1, tid);

    for (int i = tid; i < 1024; i += 512) cw[i] = w0[576 * 256 + i];
    for (int i = tid; i < 256; i += 512) {
        bsm[i] = b1[i]; bsm[256 + i] = b2[i]; bsm[512 + i] = b3[i];
    }
    for (int i = tid; i < 768; i += 512) w4s[i] = w4[i];
    if (tid < 3) b4s[tid] = b4[tid];

    // ---- geometry: 4 threads per row ----
    int row  = tid >> 2;
    int part = tid & 3;
    int R  = blockIdx.x * 128 + row;
    int gq = R >> 2;
    int s  = R & 3;
    int b  = gq >> 16;

    float c0  = coord[(size_t)gq * 2 + 0];
    float c1  = coord[(size_t)gq * 2 + 1];
    float ce0 = cell[(size_t)gq * 2 + 0] * 128.0f;
    float ce1 = cell[(size_t)gq * 2 + 1] * 128.0f;
    float vx = (s & 2) ? 1.0f : -1.0f;
    float vy = (s & 1) ? 1.0f : -1.0f;

    const float RXY = 1.0f / 128.0f;
    const float LIM = 1.0f - 1e-6f;
    float cx = c0 + vx * RXY; cx = __fadd_rn(cx, 1e-6f);
    cx = fminf(fmaxf(cx, -LIM), LIM);
    float cy = c1 + vy * RXY; cy = __fadd_rn(cy, 1e-6f);
    cy = fminf(fmaxf(cy, -LIM), LIM);
    float fx = __fmul_rn(__fmul_rn(__fadd_rn(cx, 1.0f), 128.0f), 0.5f);
    float fy = __fmul_rn(__fmul_rn(__fadd_rn(cy, 1.0f), 128.0f), 0.5f);
    int ix = (int)fminf(fmaxf(floorf(fx), 0.0f), 127.0f);
    int iy = (int)fminf(fmaxf(floorf(fy), 0.0f), 127.0f);
    float qx = -1.0f + (2.0f * (float)ix + 1.0f) * (1.0f / 128.0f);
    float qy = -1.0f + (2.0f * (float)iy + 1.0f) * (1.0f / 128.0f);
    float rel0 = __fmul_rn(__fsub_rn(c0, qx), 128.0f);
    float rel1 = __fmul_rn(__fsub_rn(c1, qy), 128.0f);
    float area = fabsf(rel0 * rel1) + 1e-9f;

    __syncthreads();   // cw ready

    // ---- layer-0 input: gather z + rank-4 correction + relu -> As hi/lo (fp16) ----
    {
        const float4* zrow = (const float4*)(g_z + ((size_t)((b * Hh + ix) * Ww + iy)) * HID);
        const float4* cwa  = (const float4*)cw;
        char* ph = smc + OFF_ASH + row * 528 + part * 128;
        char* pl = smc + OFF_ASL + row * 528 + part * 128;
#pragma unroll 4
        for (int m = 0; m < 16; ++m) {
            int c4 = part * 16 + m;
            float4 z  = zrow[c4];
            float4 a0 = cwa[c4];
            float4 a1 = cwa[64 + c4];
            float4 a2 = cwa[128 + c4];
            float4 a3 = cwa[192 + c4];
            float v0 = fmaxf(z.x + rel0 * a0.x + rel1 * a1.x + ce0 * a2.x + ce1 * a3.x, 0.f);
            float v1 = fmaxf(z.y + rel0 * a0.y + rel1 * a1.y + ce0 * a2.y + ce1 * a3.y, 0.f);
            float v2 = fmaxf(z.z + rel0 * a0.z + rel1 * a1.z + ce0 * a2.z + ce1 * a3.z, 0.f);
            float v3 = fmaxf(z.w + rel0 * a0.w + rel1 * a1.w + ce0 * a2.w + ce1 * a3.w, 0.f);
            __half h0 = __float2half_rn(v0);
            __half h1 = __float2half_rn(v1);
            __half h2 = __float2half_rn(v2);
            __half h3 = __float2half_rn(v3);
            __half2 hp0 = __halves2half2(h0, h1);
            __half2 hp1 = __halves2half2(h2, h3);
            ((uint32_t*)(ph + m * 8))[0] = *reinterpret_cast<uint32_t*>(&hp0);
            ((uint32_t*)(ph + m * 8))[1] = *reinterpret_cast<uint32_t*>(&hp1);
            __half2 lp0 = __floats2half2_rn(v0 - __half2float(h0), v1 - __half2float(h1));
            __half2 lp1 = __floats2half2_rn(v2 - __half2float(h2), v3 - __half2float(h3));
            ((uint32_t*)(pl + m * 8))[0] = *reinterpret_cast<uint32_t*>(&lp0);
            ((uint32_t*)(pl + m * 8))[1] = *reinterpret_cast<uint32_t*>(&lp1);
        }
    }

    // ---- ldmatrix lane base addresses ----
    int arow = (lane & 7) + ((lane >> 3) & 1) * 8;
    int acol = (lane >> 4) * 16;
    uint32_t ahi0 = smem_base + OFF_ASH + (uint32_t)((wm * 32 + arow) * 528 + acol);
    uint32_t ahi1 = ahi0 + 16 * 528;
    uint32_t alo0 = ahi0 + (OFF_ASL - OFF_ASH);
    uint32_t alo1 = alo0 + 16 * 528;
    uint32_t wbl  = ws_s + lane * 8;

    // ================= layer 0: two-term (hi f32-acc + lo f16-acc) =================
    {
        float acc[2][8][4];
        uint32_t lac[2][8][2];
#pragma unroll
        for (int mt = 0; mt < 2; ++mt)
#pragma unroll
            for (int nt = 0; nt < 8; ++nt) {
#pragma unroll
                for (int i = 0; i < 4; ++i) acc[mt][nt][i] = 0.f;
                lac[mt][nt][0] = 0u; lac[mt][nt][1] = 0u;
            }

#pragma unroll 1
        for (int ch = 0; ch < 8; ++ch) {
            cpa_wait1();
            __syncthreads();
            prefetch_chunk(ws_s, ch + 2, tid);
            uint32_t wb = wbl + (uint32_t)((ch % 3) * 16384);
#pragma unroll
            for (int ki = 0; ki < 2; ++ki) {
                int ks = ch * 2 + ki;
                uint32_t ah0, ah1, ah2, ah3, ag0, ag1, ag2, ag3;
                uint32_t al0, al1, al2, al3, am0, am1, am2, am3;
                ldmA(ah0, ah1, ah2, ah3, ahi0 + ks * 32);
                ldmA(ag0, ag1, ag2, ag3, ahi1 + ks * 32);
                ldmA(al0, al1, al2, al3, alo0 + ks * 32);
                ldmA(am0, am1, am2, am3, alo1 + ks * 32);
                uint32_t base = wb + (uint32_t)(ki * 8192) + (uint32_t)(wn * 2048);
#pragma unroll
                for (int nt = 0; nt < 8; ++nt) {
                    uint32_t bh0, bh1;
                    ldsv2(bh0, bh1, base + nt * 256);
                    mma16816(acc[0][nt][0], acc[0][nt][1], acc[0][nt][2], acc[0][nt][3],
                             ah0, ah1, ah2, ah3, bh0, bh1);
                    mma16816(acc[1][nt][0], acc[1][nt][1], acc[1][nt][2], acc[1][nt][3],
                             ag0, ag1, ag2, ag3, bh0, bh1);
                    mma16816h(lac[0][nt][0], lac[0][nt][1],
                              al0, al1, al2, al3, bh0, bh1);
                    mma16816h(lac[1][nt][0], lac[1][nt][1],
                              am0, am1, am2, am3, bh0, bh1);
                }
            }
        }
        __syncthreads();   // all warps done reading A before epilogue overwrites it

        // epilogue: relu(acc + lo + b1) -> fp16 hi only
#pragma unroll
        for (int mt = 0; mt < 2; ++mt) {
            int r0 = wm * 32 + mt * 16 + (lane >> 2);
#pragma unroll
            for (int nt = 0; nt < 8; ++nt) {
                int c = wn * 64 + nt * 8 + (lane & 3) * 2;
                float bb0 = bsm[c];
                float bb1 = bsm[c + 1];
                float2 lo0 = __half22float2(*reinterpret_cast<__half2*>(&lac[mt][nt][0]));
                float2 lo1 = __half22float2(*reinterpret_cast<__half2*>(&lac[mt][nt][1]));
#pragma unroll
                for (int hh = 0; hh < 2; ++hh) {
                    int r = r0 + hh * 8;
                    float lx = hh ? lo1.x : lo0.x;
                    float ly = hh ? lo1.y : lo0.y;
                    float v0 = fmaxf(acc[mt][nt][2 * hh]     + lx + bb0, 0.f);
                    float v1 = fmaxf(acc[mt][nt][2 * hh + 1] + ly + bb1, 0.f);
                    __half2 hp = __floats2half2_rn(v0, v1);
                    *(uint32_t*)(smc + OFF_ASH + r * 528 + c * 2) =
                        *reinterpret_cast<uint32_t*>(&hp);
                }
            }
        }
    }

    // ================= layer 1: hi-only, straight-line =================
    {
        float acc[2][8][4];
#pragma unroll
        for (int mt = 0; mt < 2; ++mt)
#pragma unroll
            for (int nt = 0; nt < 8; ++nt)
#pragma unroll
                for (int i = 0; i < 4; ++i) acc[mt][nt][i] = 0.f;

#pragma unroll 1
        for (int ch = 0; ch < 8; ++ch) {
            int q = 8 + ch;
            cpa_wait1();
            __syncthreads();
            prefetch_chunk(ws_s, q + 2, tid);
            uint32_t wb = wbl + (uint32_t)((q % 3) * 16384);
#pragma unroll
            for (int ki = 0; ki < 2; ++ki) {
                int ks = ch * 2 + ki;
                uint32_t ah0, ah1, ah2, ah3, ag0, ag1, ag2, ag3;
                ldmA(ah0, ah1, ah2, ah3, ahi0 + ks * 32);
                ldmA(ag0, ag1, ag2, ag3, ahi1 + ks * 32);
                uint32_t base = wb + (uint32_t)(ki * 8192) + (uint32_t)(wn * 2048);
#pragma unroll
                for (int nt = 0; nt < 8; ++nt) {
                    uint32_t bh0, bh1;
                    ldsv2(bh0, bh1, base + nt * 256);
                    mma16816(acc[0][nt][0], acc[0][nt][1], acc[0][nt][2], acc[0][nt][3],
                             ah0, ah1, ah2, ah3, bh0, bh1);
                    mma16816(acc[1][nt][0], acc[1][nt][1], acc[1][nt][2], acc[1][nt][3],
                             ag0, ag1, ag2, ag3, bh0, bh1);
                }
            }
        }
        __syncthreads();

        // epilogue: relu(acc + b2) -> fp16 hi
#pragma unroll
        for (int mt = 0; mt < 2; ++mt) {
            int r0 = wm * 32 + mt * 16 + (lane >> 2);
#pragma unroll
            for (int nt = 0; nt < 8; ++nt) {
                int c = wn * 64 + nt * 8 + (lane & 3) * 2;
                float bb0 = bsm[256 + c];
                float bb1 = bsm[256 + c + 1];
#pragma unroll
                for (int hh = 0; hh < 2; ++hh) {
                    int r = r0 + hh * 8;
                    float v0 = fmaxf(acc[mt][nt][2 * hh]     + bb0, 0.f);
                    float v1 = fmaxf(acc[mt][nt][2 * hh + 1] + bb1, 0.f);
                    __half2 hp = __floats2half2_rn(v0, v1);
                    *(uint32_t*)(smc + OFF_ASH + r * 528 + c * 2) =
                        *reinterpret_cast<uint32_t*>(&hp);
                }
            }
        }
    }

    // ================= layer 2: hi-only, straight-line, -> fp32 scratch =================
    {
        float acc[2][8][4];
#pragma unroll
        for (int mt = 0; mt < 2; ++mt)
#pragma unroll
            for (int nt = 0; nt < 8; ++nt)
#pragma unroll
                for (int i = 0; i < 4; ++i) acc[mt][nt][i] = 0.f;

#pragma unroll 1
        for (int ch = 0; ch < 8; ++ch) {
            int q = 16 + ch;
            if (q + 1 < 24) cpa_wait1(); else cpa_wait0();
            __syncthreads();
            if (q + 2 < 24) prefetch_chunk(ws_s, q + 2, tid);
            uint32_t wb = wbl + (uint32_t)((q % 3) * 16384);
#pragma unroll
            for (int ki = 0; ki < 2; ++ki) {
                int ks = ch * 2 + ki;
                uint32_t ah0, ah1, ah2, ah3, ag0, ag1, ag2, ag3;
                ldmA(ah0, ah1, ah2, ah3, ahi0 + ks * 32);
                ldmA(ag0, ag1, ag2, ag3, ahi1 + ks * 32);
                uint32_t base = wb + (uint32_t)(ki * 8192) + (uint32_t)(wn * 2048);
#pragma unroll
                for (int nt = 0; nt < 8; ++nt) {
                    uint32_t bh0, bh1;
                    ldsv2(bh0, bh1, base + nt * 256);
                    mma16816(acc[0][nt][0], acc[0][nt][1], acc[0][nt][2], acc[0][nt][3],
                             ah0, ah1, ah2, ah3, bh0, bh1);
                    mma16816(acc[1][nt][0], acc[1][nt][1], acc[1][nt][2], acc[1][nt][3],
                             ag0, ag1, ag2, ag3, bh0, bh1);
                }
            }
        }
        __syncthreads();

        // epilogue -> fp32 scratch
        float* As32 = (float*)(smc + OFF_ASH);
#pragma unroll
        for (int mt = 0; mt < 2; ++mt) {
            int r0 = wm * 32 + mt * 16 + (lane >> 2);
#pragma unroll
            for (int nt = 0; nt < 8; ++nt) {
                int c = wn * 64 + nt * 8 + (lane & 3) * 2;
                float bb0 = bsm[512 + c];
                float bb1 = bsm[512 + c + 1];
#pragma unroll
                for (int hh = 0; hh < 2; ++hh) {
                    int r = r0 + hh * 8;
                    As32[r * 260 + c]     = fmaxf(acc[mt][nt][2 * hh]     + bb0, 0.f);
                    As32[r * 260 + c + 1] = fmaxf(acc[mt][nt][2 * hh + 1] + bb1, 0.f);
                }
            }
        }
        __syncthreads();
    }

    // ---- head + ensemble ----
    {
        const float* As32 = (const float*)(smc + OFF_ASH);
        const float* arow_p = As32 + row * 260 + part * 64;
        float a0 = 0.f, a1 = 0.f, a2 = 0.f;
#pragma unroll 8
        for (int k = 0; k < 64; ++k) {
            float a = arow_p[k];
            int kg = part * 64 + k;
            a0 += a * w4s[kg * 3 + 0];
            a1 += a * w4s[kg * 3 + 1];
            a2 += a * w4s[kg * 3 + 2];
        }
        a0 += __shfl_xor_sync(0xFFFFFFFFu, a0, 1);
        a0 += __shfl_xor_sync(0xFFFFFFFFu, a0, 2);
        a1 += __shfl_xor_sync(0xFFFFFFFFu, a1, 1);
        a1 += __shfl_xor_sync(0xFFFFFFFFu, a1, 2);
        a2 += __shfl_xor_sync(0xFFFFFFFFu, a2, 1);
        a2 += __shfl_xor_sync(0xFFFFFFFFu, a2, 2);
        a0 += b4s[0]; a1 += b4s[1]; a2 += b4s[2];

        float aswap = __shfl_xor_sync(0xFFFFFFFFu, area, 12);
        float t1 = area + __shfl_xor_sync(0xFFFFFFFFu, area, 4);
        float tot = t1 + __shfl_xor_sync(0xFFFFFFFFu, t1, 8);
        float o0 = a0 * aswap, o1 = a1 * aswap, o2 = a2 * aswap;
        o0 += __shfl_xor_sync(0xFFFFFFFFu, o0, 4);
        o0 += __shfl_xor_sync(0xFFFFFFFFu, o0, 8);
        o1 += __shfl_xor_sync(0xFFFFFFFFu, o1, 4);
        o1 += __shfl_xor_sync(0xFFFFFFFFu, o1, 8);
        o2 += __shfl_xor_sync(0xFFFFFFFFu, o2, 4);
        o2 += __shfl_xor_sync(0xFFFFFFFFu, o2, 8);
        if ((tid & 15) == 0) {
            int gqo = blockIdx.x * 32 + (tid >> 4);
            out[(size_t)gqo * 3 + 0] = o0 / tot;
            out[(size_t)gqo * 3 + 1] = o1 / tot;
            out[(size_t)gqo * 3 + 2] = o2 / tot;
        }
    }
}

extern "C" void kernel_launch(void* const* d_in, const int* in_sizes, int n_in,
                              void* d_out, int out_size)
{
    const float* feat  = (const float*)d_in[0];
    const float* coord = (const float*)d_in[1];
    const float* cell  = (const float*)d_in[2];
    const float* w0 = (const float*)d_in[3];
    const float* b0 = (const float*)d_in[4];
    const float* w1 = (const float*)d_in[5];
    const float* b1 = (const float*)d_in[6];
    const float* w2 = (const float*)d_in[7];
    const float* b2 = (const float*)d_in[8];
    const float* w3 = (const float*)d_in[9];
    const float* b3 = (const float*)d_in[10];
    const float* w4 = (const float*)d_in[11];
    const float* b4 = (const float*)d_in[12];
    float* out = (float*)d_out;

    int conv_smem = (6400 + 9216) * 4;
    cudaFuncSetAttribute((const void*)conv_kernel,
                         cudaFuncAttributeMaxDynamicSharedMemorySize, conv_smem);
    cudaFuncSetAttribute((const void*)mlp_mma_kernel,
                         cudaFuncAttributeMaxDynamicSharedMemorySize, SMEM_TOT);

    prep_kernel<<<768, 256>>>(w1, w2, w3);
    conv_kernel<<<512, 256, conv_smem>>>(feat, w0, b0);
    mlp_mma_kernel<<<4096, 512, SMEM_TOT>>>(coord, cell, w0, b1, b2, b3, w4, b4, out);
}

// round 15
// speedup vs baseline: 1.7502x; 1.1086x over previous
#include <cuda_runtime.h>
#include <cuda_fp16.h>
#include <cstdint>

#define Bsz 2
#define Cch 64
#define Hh  128
#define Ww  128
#define HID 256

// 32 MB scratch for conv3x3(feat, W0) + b0, layout [B][H][W][256]
__device__ float g_z[Bsz * Hh * Ww * HID];
// Pre-packed fp16 weights in mma.sync B-fragment layout: 24 chunks x 16KB
__device__ __half g_wb[3 * 65536];

// ---------------- generic helpers ----------------
__device__ __forceinline__ unsigned long long pack2(float a, float b) {
    unsigned long long r;
    asm("mov.b64 %0, {%1, %2};" : "=l"(r) : "f"(a), "f"(b));
    return r;
}
__device__ __forceinline__ unsigned long long fma2(unsigned long long a,
                                                   unsigned long long b,
                                                   unsigned long long c) {
    unsigned long long d;
    asm("fma.rn.f32x2 %0, %1, %2, %3;" : "=l"(d) : "l"(a), "l"(b), "l"(c));
    return d;
}
__device__ __forceinline__ float2 unpack2(unsigned long long a) {
    float lo, hi;
    asm("mov.b64 {%0, %1}, %2;" : "=f"(lo), "=f"(hi) : "l"(a));
    return make_float2(lo, hi);
}
__device__ __forceinline__ uint32_t s2u(const void* p) {
    uint32_t a;
    asm("{ .reg .u64 t; cvta.to.shared.u64 t, %1; cvt.u32.u64 %0, t; }" : "=r"(a) : "l"(p));
    return a;
}
__device__ __forceinline__ void cpa16(uint32_t d, const void* s) {
    asm volatile("cp.async.ca.shared.global [%0], [%1], 16;" :: "r"(d), "l"(s));
}
__device__ __forceinline__ void cpa_commit() { asm volatile("cp.async.commit_group;"); }
__device__ __forceinline__ void cpa_wait1()  { asm volatile("cp.async.wait_group 1;"); }
__device__ __forceinline__ void cpa_wait0()  { asm volatile("cp.async.wait_group 0;"); }

__device__ __forceinline__ void ldmA(uint32_t& a0, uint32_t& a1, uint32_t& a2,
                                     uint32_t& a3, uint32_t addr) {
    asm volatile("ldmatrix.sync.aligned.m8n8.x4.shared.b16 {%0,%1,%2,%3}, [%4];"
                 : "=r"(a0), "=r"(a1), "=r"(a2), "=r"(a3) : "r"(addr));
}
__device__ __forceinline__ void ldsv2(uint32_t& b0, uint32_t& b1, uint32_t addr) {
    asm volatile("ld.shared.v2.b32 {%0,%1}, [%2];" : "=r"(b0), "=r"(b1) : "r"(addr));
}
__device__ __forceinline__ void mma16816(float& d0, float& d1, float& d2, float& d3,
                                         uint32_t a0, uint32_t a1, uint32_t a2, uint32_t a3,
                                         uint32_t b0, uint32_t b1) {
    asm volatile("mma.sync.aligned.m16n8k16.row.col.f32.f16.f16.f32 "
                 "{%0,%1,%2,%3}, {%4,%5,%6,%7}, {%8,%9}, {%0,%1,%2,%3};"
                 : "+f"(d0), "+f"(d1), "+f"(d2), "+f"(d3)
                 : "r"(a0), "r"(a1), "r"(a2), "r"(a3), "r"(b0), "r"(b1));
}

// ---------------- kernel 0: weight -> fp16 B-fragment layout ----------------
__global__ void prep_kernel(const float* __restrict__ w1,
                            const float* __restrict__ w2,
                            const float* __restrict__ w3)
{
    int t = blockIdx.x * 256 + threadIdx.x;
    if (t >= 3 * 65536) return;
    int l  = t >> 16;
    int kn = t & 65535;
    int k  = kn >> 8;
    int n  = kn & 255;
    const float* w = (l == 0) ? w1 : (l == 1) ? w2 : w3;
    __half o = __float2half_rn(w[k * 256 + n]);
    int ks = k >> 4, kk = k & 15;
    int nt = n >> 3, c = n & 7;
    int lane = c * 4 + ((kk >> 1) & 3);
    int reg  = kk >> 3;
    int half = kk & 1;
    size_t byte = (size_t)l * 131072 + (ks * 32 + nt) * 256
                + lane * 8 + reg * 4 + half * 2;
    g_wb[byte >> 1] = o;
}

// ---------------- kernel 1: z = conv3x3(feat, W0) + b0 ----------------
__device__ __forceinline__ void prefetch12(uint32_t ws_s, const float* wbase, int ch, int tid) {
    const float* g = wbase + (size_t)ch * 3072;
    uint32_t d = ws_s + (uint32_t)((ch % 3) * 12288);
#pragma unroll
    for (int m = 0; m < 3; ++m) {
        int i4 = tid + 256 * m;
        cpa16(d + i4 * 16, g + i4 * 4);
    }
    cpa_commit();
}

__global__ __launch_bounds__(256, 2) void conv_kernel(
    const float* __restrict__ feat, const float* __restrict__ w0,
    const float* __restrict__ b0)
{
    extern __shared__ float sm[];
    float* fs = sm;            // 64 ch x (10x10) patch
    float* ws = sm + 6400;     // 3 x 3072 weight buffers

    int tid = threadIdx.x;
    int blk = blockIdx.x;
    int bb  = blk >> 8;
    int rem = blk & 255;
    int by = rem >> 4, bx = rem & 15;
    int y0 = by * 8 - 1, x0 = bx * 8 - 1;

    uint32_t ws_s = s2u(ws);
    prefetch12(ws_s, w0, 0, tid);
    prefetch12(ws_s, w0, 1, tid);

    for (int idx = tid; idx < 6400; idx += 256) {
        int c  = idx / 100;
        int p  = idx - c * 100;
        int pr = p / 10;
        int pi = pr + y0;
        int pj = (p - pr * 10) + x0;
        float v = 0.f;
        if ((unsigned)pi < Hh && (unsigned)pj < Ww)
            v = feat[((size_t)(bb * Cch + c) * Hh + pi) * Ww + pj];
        fs[idx] = v;
    }

    int r  = tid >> 5;
    int tx = tid & 31;

    unsigned long long acc[8][4];
#pragma unroll
    for (int i = 0; i < 8; ++i)
#pragma unroll
        for (int j = 0; j < 4; ++j) acc[i][j] = 0ull;

    int c_ = 0, ki = 0;
#pragma unroll 1
    for (int ch = 0; ch < 48; ++ch) {
        if (ch + 1 < 48) cpa_wait1(); else cpa_wait0();
        __syncthreads();
        if (ch + 2 < 48) prefetch12(ws_s, w0, ch + 2, tid);
        const float* wsb = ws + (ch % 3) * 3072;
#pragma unroll
        for (int g = 0; g < 4; ++g) {
            const float* ab = fs + c_ * 100 + (r + ki) * 10;
            unsigned long long a2row[10];
#pragma unroll
            for (int t2 = 0; t2 < 10; ++t2) { float a = ab[t2]; a2row[t2] = pack2(a, a); }
#pragma unroll
            for (int kj = 0; kj < 3; ++kj) {
#pragma unroll
                for (int j = 0; j < 4; ++j) {
                    unsigned long long w2 =
                        *(const unsigned long long*)(wsb + (g * 3 + kj) * 256 + 2 * (tx + 32 * j));
#pragma unroll
                    for (int i = 0; i < 8; ++i)
                        acc[i][j] = fma2(a2row[kj + i], w2, acc[i][j]);
                }
            }
            if (++ki == 3) { ki = 0; ++c_; }
        }
    }

    int gy = by * 8 + r;
#pragma unroll
    for (int j = 0; j < 4; ++j) {
        float2 bb2 = ((const float2*)b0)[tx + 32 * j];
#pragma unroll
        for (int i = 0; i < 8; ++i) {
            float2 v = unpack2(acc[i][j]);
            v.x += bb2.x; v.y += bb2.y;
            int gx = bx * 8 + i;
            *(float2*)(g_z + ((size_t)(bb * Hh + gy) * Ww + gx) * HID + 2 * tx + 64 * j) = v;
        }
    }
}

// ---------------- kernel 2: HMMA MLP (all layers hi-only fp16) ----------------
// grid = 4096, block = 512 (16 warps, 4x4). CTA: 128 rows x 256 cols, K=256.
// STRUCTURE RULE (R10/R12): each layer = straight-line block, unbranched epilogue.
// LAYOUT RULE (R14 crash): the OFF_ASH region doubles as a 128x260 fp32 scratch
// (133120 B) for the final layer + head — size it for the LARGER footprint.
#define OFF_WBUF 0          // 3 x 16KB weight buffers (49152)
#define OFF_ASH  49152      // A fp16 (67584 B) / fp32 scratch 128x260 (133120 B)
#define OFF_BSM  182272     // b1,b2,b3: 768 f32
#define OFF_W4   185344     // w4: 768 f32
#define OFF_B4   188416     // b4: 4 f32
#define OFF_CW   188432     // W0 rows 576..579: 1024 f32
#define SMEM_TOT 192528

__device__ __forceinline__ void prefetch_chunk(uint32_t ws_s, int q, int tid) {
    const char* src = (const char*)g_wb + (size_t)q * 16384;
    uint32_t d = ws_s + (uint32_t)((q % 3) * 16384);
#pragma unroll
    for (int m = 0; m < 2; ++m) {
        int o = (tid + 512 * m) * 16;
        cpa16(d + o, src + o);
    }
    cpa_commit();
}

__global__ __launch_bounds__(512, 1) void mlp_mma_kernel(
    const float* __restrict__ coord, const float* __restrict__ cell,
    const float* __restrict__ w0,
    const float* __restrict__ b1, const float* __restrict__ b2,
    const float* __restrict__ b3,
    const float* __restrict__ w4, const float* __restrict__ b4,
    float* __restrict__ out)
{
    extern __shared__ char smc[];
    float* bsm = (float*)(smc + OFF_BSM);
    float* w4s = (float*)(smc + OFF_W4);
    float* b4s = (float*)(smc + OFF_B4);
    float* cw  = (float*)(smc + OFF_CW);

    int tid  = threadIdx.x;
    int lane = tid & 31;
    int wid  = tid >> 5;
    int wm   = wid >> 2;    // rows wm*32..+31
    int wn   = wid & 3;     // cols wn*64..+63

    uint32_t smem_base = s2u(smc);
    uint32_t ws_s = smem_base + OFF_WBUF;

    prefetch_chunk(ws_s, 0, tid);
    prefetch_chunk(ws_s, 1, tid);

    for (int i = tid; i < 1024; i += 512) cw[i] = w0[576 * 256 + i];
    for (int i = tid; i < 256; i += 512) {
        bsm[i] = b1[i]; bsm[256 + i] = b2[i]; bsm[512 + i] = b3[i];
    }
    for (int i = tid; i < 768; i += 512) w4s[i] = w4[i];
    if (tid < 3) b4s[tid] = b4[tid];

    // ---- geometry: 4 threads per row ----
    int row  = tid >> 2;
    int part = tid & 3;
    int R  = blockIdx.x * 128 + row;
    int gq = R >> 2;
    int s  = R & 3;
    int b  = gq >> 16;

    float c0  = coord[(size_t)gq * 2 + 0];
    float c1  = coord[(size_t)gq * 2 + 1];
    float ce0 = cell[(size_t)gq * 2 + 0] * 128.0f;
    float ce1 = cell[(size_t)gq * 2 + 1] * 128.0f;
    float vx = (s & 2) ? 1.0f : -1.0f;
    float vy = (s & 1) ? 1.0f : -1.0f;

    const float RXY = 1.0f / 128.0f;
    const float LIM = 1.0f - 1e-6f;
    float cx = c0 + vx * RXY; cx = __fadd_rn(cx, 1e-6f);
    cx = fminf(fmaxf(cx, -LIM), LIM);
    float cy = c1 + vy * RXY; cy = __fadd_rn(cy, 1e-6f);
    cy = fminf(fmaxf(cy, -LIM), LIM);
    float fx = __fmul_rn(__fmul_rn(__fadd_rn(cx, 1.0f), 128.0f), 0.5f);
    float fy = __fmul_rn(__fmul_rn(__fadd_rn(cy, 1.0f), 128.0f), 0.5f);
    int ix = (int)fminf(fmaxf(floorf(fx), 0.0f), 127.0f);
    int iy = (int)fminf(fmaxf(floorf(fy), 0.0f), 127.0f);
    float qx = -1.0f + (2.0f * (float)ix + 1.0f) * (1.0f / 128.0f);
    float qy = -1.0f + (2.0f * (float)iy + 1.0f) * (1.0f / 128.0f);
    float rel0 = __fmul_rn(__fsub_rn(c0, qx), 128.0f);
    float rel1 = __fmul_rn(__fsub_rn(c1, qy), 128.0f);
    float area = fabsf(rel0 * rel1) + 1e-9f;

    __syncthreads();   // cw ready

    // ---- layer-0 input: gather z + rank-4 correction + relu -> As hi (fp16) ----
    {
        const float4* zrow = (const float4*)(g_z + ((size_t)((b * Hh + ix) * Ww + iy)) * HID);
        const float4* cwa  = (const float4*)cw;
        char* ph = smc + OFF_ASH + row * 528 + part * 128;
#pragma unroll 4
        for (int m = 0; m < 16; ++m) {
            int c4 = part * 16 + m;
            float4 z  = zrow[c4];
            float4 a0 = cwa[c4];
            float4 a1 = cwa[64 + c4];
            float4 a2 = cwa[128 + c4];
            float4 a3 = cwa[192 + c4];
            float v0 = fmaxf(z.x + rel0 * a0.x + rel1 * a1.x + ce0 * a2.x + ce1 * a3.x, 0.f);
            float v1 = fmaxf(z.y + rel0 * a0.y + rel1 * a1.y + ce0 * a2.y + ce1 * a3.y, 0.f);
            float v2 = fmaxf(z.z + rel0 * a0.z + rel1 * a1.z + ce0 * a2.z + ce1 * a3.z, 0.f);
            float v3 = fmaxf(z.w + rel0 * a0.w + rel1 * a1.w + ce0 * a2.w + ce1 * a3.w, 0.f);
            __half2 hp0 = __floats2half2_rn(v0, v1);
            __half2 hp1 = __floats2half2_rn(v2, v3);
            ((uint32_t*)(ph + m * 8))[0] = *reinterpret_cast<uint32_t*>(&hp0);
            ((uint32_t*)(ph + m * 8))[1] = *reinterpret_cast<uint32_t*>(&hp1);
        }
    }

    // ---- ldmatrix lane base addresses ----
    int arow = (lane & 7) + ((lane >> 3) & 1) * 8;
    int acol = (lane >> 4) * 16;
    uint32_t ahi0 = smem_base + OFF_ASH + (uint32_t)((wm * 32 + arow) * 528 + acol);
    uint32_t ahi1 = ahi0 + 16 * 528;
    uint32_t wbl  = ws_s + lane * 8;

    // ================= layer 0: hi-only, straight-line =================
    {
        float acc[2][8][4];
#pragma unroll
        for (int mt = 0; mt < 2; ++mt)
#pragma unroll
            for (int nt = 0; nt < 8; ++nt)
#pragma unroll
                for (int i = 0; i < 4; ++i) acc[mt][nt][i] = 0.f;

#pragma unroll 1
        for (int ch = 0; ch < 8; ++ch) {
            cpa_wait1();
            __syncthreads();
            prefetch_chunk(ws_s, ch + 2, tid);
            uint32_t wb = wbl + (uint32_t)((ch % 3) * 16384);
#pragma unroll
            for (int ki = 0; ki < 2; ++ki) {
                int ks = ch * 2 + ki;
                uint32_t ah0, ah1, ah2, ah3, ag0, ag1, ag2, ag3;
                ldmA(ah0, ah1, ah2, ah3, ahi0 + ks * 32);
                ldmA(ag0, ag1, ag2, ag3, ahi1 + ks * 32);
                uint32_t base = wb + (uint32_t)(ki * 8192) + (uint32_t)(wn * 2048);
#pragma unroll
                for (int nt = 0; nt < 8; ++nt) {
                    uint32_t bh0, bh1;
                    ldsv2(bh0, bh1, base + nt * 256);
                    mma16816(acc[0][nt][0], acc[0][nt][1], acc[0][nt][2], acc[0][nt][3],
                             ah0, ah1, ah2, ah3, bh0, bh1);
                    mma16816(acc[1][nt][0], acc[1][nt][1], acc[1][nt][2], acc[1][nt][3],
                             ag0, ag1, ag2, ag3, bh0, bh1);
                }
            }
        }
        __syncthreads();   // all warps done reading A before epilogue overwrites it

        // epilogue: relu(acc + b1) -> fp16 hi
#pragma unroll
        for (int mt = 0; mt < 2; ++mt) {
            int r0 = wm * 32 + mt * 16 + (lane >> 2);
#pragma unroll
            for (int nt = 0; nt < 8; ++nt) {
                int c = wn * 64 + nt * 8 + (lane & 3) * 2;
                float bb0 = bsm[c];
                float bb1 = bsm[c + 1];
#pragma unroll
                for (int hh = 0; hh < 2; ++hh) {
                    int r = r0 + hh * 8;
                    float v0 = fmaxf(acc[mt][nt][2 * hh]     + bb0, 0.f);
                    float v1 = fmaxf(acc[mt][nt][2 * hh + 1] + bb1, 0.f);
                    __half2 hp = __floats2half2_rn(v0, v1);
                    *(uint32_t*)(smc + OFF_ASH + r * 528 + c * 2) =
                        *reinterpret_cast<uint32_t*>(&hp);
                }
            }
        }
    }

    // ================= layer 1: hi-only, straight-line =================
    {
        float acc[2][8][4];
#pragma unroll
        for (int mt = 0; mt < 2; ++mt)
#pragma unroll
            for (int nt = 0; nt < 8; ++nt)
#pragma unroll
                for (int i = 0; i < 4; ++i) acc[mt][nt][i] = 0.f;

#pragma unroll 1
        for (int ch = 0; ch < 8; ++ch) {
            int q = 8 + ch;
            cpa_wait1();
            __syncthreads();
            prefetch_chunk(ws_s, q + 2, tid);
            uint32_t wb = wbl + (uint32_t)((q % 3) * 16384);
#pragma unroll
            for (int ki = 0; ki < 2; ++ki) {
                int ks = ch * 2 + ki;
                uint32_t ah0, ah1, ah2, ah3, ag0, ag1, ag2, ag3;
                ldmA(ah0, ah1, ah2, ah3, ahi0 + ks * 32);
                ldmA(ag0, ag1, ag2, ag3, ahi1 + ks * 32);
                uint32_t base = wb + (uint32_t)(ki * 8192) + (uint32_t)(wn * 2048);
#pragma unroll
                for (int nt = 0; nt < 8; ++nt) {
                    uint32_t bh0, bh1;
                    ldsv2(bh0, bh1, base + nt * 256);
                    mma16816(acc[0][nt][0], acc[0][nt][1], acc[0][nt][2], acc[0][nt][3],
                             ah0, ah1, ah2, ah3, bh0, bh1);
                    mma16816(acc[1][nt][0], acc[1][nt][1], acc[1][nt][2], acc[1][nt][3],
                             ag0, ag1, ag2, ag3, bh0, bh1);
                }
            }
        }
        __syncthreads();

        // epilogue: relu(acc + b2) -> fp16 hi
#pragma unroll
        for (int mt = 0; mt < 2; ++mt) {
            int r0 = wm * 32 + mt * 16 + (lane >> 2);
#pragma unroll
            for (int nt = 0; nt < 8; ++nt) {
                int c = wn * 64 + nt * 8 + (lane & 3) * 2;
                float bb0 = bsm[256 + c];
                float bb1 = bsm[256 + c + 1];
#pragma unroll
                for (int hh = 0; hh < 2; ++hh) {
                    int r = r0 + hh * 8;
                    float v0 = fmaxf(acc[mt][nt][2 * hh]     + bb0, 0.f);
                    float v1 = fmaxf(acc[mt][nt][2 * hh + 1] + bb1, 0.f);
                    __half2 hp = __floats2half2_rn(v0, v1);
                    *(uint32_t*)(smc + OFF_ASH + r * 528 + c * 2) =
                        *reinterpret_cast<uint32_t*>(&hp);
                }
            }
        }
    }

    // ================= layer 2: hi-only, straight-line, -> fp32 scratch =================
    {
        float acc[2][8][4];
#pragma unroll
        for (int mt = 0; mt < 2; ++mt)
#pragma unroll
            for (int nt = 0; nt < 8; ++nt)
#pragma unroll
                for (int i = 0; i < 4; ++i) acc[mt][nt][i] = 0.f;

#pragma unroll 1
        for (int ch = 0; ch < 8; ++ch) {
            int q = 16 + ch;
            if (q + 1 < 24) cpa_wait1(); else cpa_wait0();
            __syncthreads();
            if (q + 2 < 24) prefetch_chunk(ws_s, q + 2, tid);
            uint32_t wb = wbl + (uint32_t)((q % 3) * 16384);
#pragma unroll
            for (int ki = 0; ki < 2; ++ki) {
                int ks = ch * 2 + ki;
                uint32_t ah0, ah1, ah2, ah3, ag0, ag1, ag2, ag3;
                ldmA(ah0, ah1, ah2, ah3, ahi0 + ks * 32);
                ldmA(ag0, ag1, ag2, ag3, ahi1 + ks * 32);
                uint32_t base = wb + (uint32_t)(ki * 8192) + (uint32_t)(wn * 2048);
#pragma unroll
                for (int nt = 0; nt < 8; ++nt) {
                    uint32_t bh0, bh1;
                    ldsv2(bh0, bh1, base + nt * 256);
                    mma16816(acc[0][nt][0], acc[0][nt][1], acc[0][nt][2], acc[0][nt][3],
                             ah0, ah1, ah2, ah3, bh0, bh1);
                    mma16816(acc[1][nt][0], acc[1][nt][1], acc[1][nt][2], acc[1][nt][3],
                             ag0, ag1, ag2, ag3, bh0, bh1);
                }
            }
        }
        __syncthreads();

        // epilogue -> fp32 scratch (133120 B region — fits by layout)
        float* As32 = (float*)(smc + OFF_ASH);
#pragma unroll
        for (int mt = 0; mt < 2; ++mt) {
            int r0 = wm * 32 + mt * 16 + (lane >> 2);
#pragma unroll
            for (int nt = 0; nt < 8; ++nt) {
                int c = wn * 64 + nt * 8 + (lane & 3) * 2;
                float bb0 = bsm[512 + c];
                float bb1 = bsm[512 + c + 1];
#pragma unroll
                for (int hh = 0; hh < 2; ++hh) {
                    int r = r0 + hh * 8;
                    As32[r * 260 + c]     = fmaxf(acc[mt][nt][2 * hh]     + bb0, 0.f);
                    As32[r * 260 + c + 1] = fmaxf(acc[mt][nt][2 * hh + 1] + bb1, 0.f);
                }
            }
        }
        __syncthreads();
    }

    // ---- head + ensemble ----
    {
        const float* As32 = (const float*)(smc + OFF_ASH);
        const float* arow_p = As32 + row * 260 + part * 64;
        float a0 = 0.f, a1 = 0.f, a2 = 0.f;
#pragma unroll 8
        for (int k = 0; k < 64; ++k) {
            float a = arow_p[k];
            int kg = part * 64 + k;
            a0 += a * w4s[kg * 3 + 0];
            a1 += a * w4s[kg * 3 + 1];
            a2 += a * w4s[kg * 3 + 2];
        }
        a0 += __shfl_xor_sync(0xFFFFFFFFu, a0, 1);
        a0 += __shfl_xor_sync(0xFFFFFFFFu, a0, 2);
        a1 += __shfl_xor_sync(0xFFFFFFFFu, a1, 1);
        a1 += __shfl_xor_sync(0xFFFFFFFFu, a1, 2);
        a2 += __shfl_xor_sync(0xFFFFFFFFu, a2, 1);
        a2 += __shfl_xor_sync(0xFFFFFFFFu, a2, 2);
        a0 += b4s[0]; a1 += b4s[1]; a2 += b4s[2];

        float aswap = __shfl_xor_sync(0xFFFFFFFFu, area, 12);
        float t1 = area + __shfl_xor_sync(0xFFFFFFFFu, area, 4);
        float tot = t1 + __shfl_xor_sync(0xFFFFFFFFu, t1, 8);
        float o0 = a0 * aswap, o1 = a1 * aswap, o2 = a2 * aswap;
        o0 += __shfl_xor_sync(0xFFFFFFFFu, o0, 4);
        o0 += __shfl_xor_sync(0xFFFFFFFFu, o0, 8);
        o1 += __shfl_xor_sync(0xFFFFFFFFu, o1, 4);
        o1 += __shfl_xor_sync(0xFFFFFFFFu, o1, 8);
        o2 += __shfl_xor_sync(0xFFFFFFFFu, o2, 4);
        o2 += __shfl_xor_sync(0xFFFFFFFFu, o2, 8);
        if ((tid & 15) == 0) {
            int gqo = blockIdx.x * 32 + (tid >> 4);
            out[(size_t)gqo * 3 + 0] = o0 / tot;
            out[(size_t)gqo * 3 + 1] = o1 / tot;
            out[(size_t)gqo * 3 + 2] = o2 / tot;
        }
    }
}

extern "C" void kernel_launch(void* const* d_in, const int* in_sizes, int n_in,
                              void* d_out, int out_size)
{
    const float* feat  = (const float*)d_in[0];
    const float* coord = (const float*)d_in[1];
    const float* cell  = (const float*)d_in[2];
    const float* w0 = (const float*)d_in[3];
    const float* b0 = (const float*)d_in[4];
    const float* w1 = (const float*)d_in[5];
    const float* b1 = (const float*)d_in[6];
    const float* w2 = (const float*)d_in[7];
    const float* b2 = (const float*)d_in[8];
    const float* w3 = (const float*)d_in[9];
    const float* b3 = (const float*)d_in[10];
    const float* w4 = (const float*)d_in[11];
    const float* b4 = (const float*)d_in[12];
    float* out = (float*)d_out;

    int conv_smem = (6400 + 9216) * 4;
    cudaFuncSetAttribute((const void*)conv_kernel,
                         cudaFuncAttributeMaxDynamicSharedMemorySize, conv_smem);
    cudaFuncSetAttribute((const void*)mlp_mma_kernel,
                         cudaFuncAttributeMaxDynamicSharedMemorySize, SMEM_TOT);

    prep_kernel<<<768, 256>>>(w1, w2, w3);
    conv_kernel<<<512, 256, conv_smem>>>(feat, w0, b0);
    mlp_mma_kernel<<<4096, 512, SMEM_TOT>>>(coord, cell, w0, b1, b2, b3, w4, b4, out);
}

// round 16
// speedup vs baseline: 1.9499x; 1.1141x over previous
#include <cuda_runtime.h>
#include <cuda_fp16.h>
#include <cstdint>

#define Bsz 2
#define Cch 64
#define Hh  128
#define Ww  128
#define HID 256

// 32 MB scratch for conv3x3(feat, W0) + b0, layout [B][H][W][256]
__device__ float g_z[Bsz * Hh * Ww * HID];
// Pre-packed fp16 weights in mma.sync B-fragment layout:
// byte = l*131072 + ks*8192 + (n>>6)*2048 + fragment(lane,reg)  (ks = k>>4)
__device__ __half g_wb[3 * 65536];

// ---------------- generic helpers ----------------
__device__ __forceinline__ unsigned long long pack2(float a, float b) {
    unsigned long long r;
    asm("mov.b64 %0, {%1, %2};" : "=l"(r) : "f"(a), "f"(b));
    return r;
}
__device__ __forceinline__ unsigned long long fma2(unsigned long long a,
                                                   unsigned long long b,
                                                   unsigned long long c) {
    unsigned long long d;
    asm("fma.rn.f32x2 %0, %1, %2, %3;" : "=l"(d) : "l"(a), "l"(b), "l"(c));
    return d;
}
__device__ __forceinline__ float2 unpack2(unsigned long long a) {
    float lo, hi;
    asm("mov.b64 {%0, %1}, %2;" : "=f"(lo), "=f"(hi) : "l"(a));
    return make_float2(lo, hi);
}
__device__ __forceinline__ uint32_t s2u(const void* p) {
    uint32_t a;
    asm("{ .reg .u64 t; cvta.to.shared.u64 t, %1; cvt.u32.u64 %0, t; }" : "=r"(a) : "l"(p));
    return a;
}
__device__ __forceinline__ void cpa16(uint32_t d, const void* s) {
    asm volatile("cp.async.ca.shared.global [%0], [%1], 16;" :: "r"(d), "l"(s));
}
__device__ __forceinline__ void cpa_commit() { asm volatile("cp.async.commit_group;"); }
__device__ __forceinline__ void cpa_wait1()  { asm volatile("cp.async.wait_group 1;"); }
__device__ __forceinline__ void cpa_wait0()  { asm volatile("cp.async.wait_group 0;"); }

__device__ __forceinline__ void ldmA(uint32_t& a0, uint32_t& a1, uint32_t& a2,
                                     uint32_t& a3, uint32_t addr) {
    asm volatile("ldmatrix.sync.aligned.m8n8.x4.shared.b16 {%0,%1,%2,%3}, [%4];"
                 : "=r"(a0), "=r"(a1), "=r"(a2), "=r"(a3) : "r"(addr));
}
__device__ __forceinline__ void mma16816(float& d0, float& d1, float& d2, float& d3,
                                         uint32_t a0, uint32_t a1, uint32_t a2, uint32_t a3,
                                         uint32_t b0, uint32_t b1) {
    asm volatile("mma.sync.aligned.m16n8k16.row.col.f32.f16.f16.f32 "
                 "{%0,%1,%2,%3}, {%4,%5,%6,%7}, {%8,%9}, {%0,%1,%2,%3};"
                 : "+f"(d0), "+f"(d1), "+f"(d2), "+f"(d3)
                 : "r"(a0), "r"(a1), "r"(a2), "r"(a3), "r"(b0), "r"(b1));
}

// ---------------- kernel 0: weight -> fp16 B-fragment layout ----------------
__global__ void prep_kernel(const float* __restrict__ w1,
                            const float* __restrict__ w2,
                            const float* __restrict__ w3)
{
    int t = blockIdx.x * 256 + threadIdx.x;
    if (t >= 3 * 65536) return;
    int l  = t >> 16;
    int kn = t & 65535;
    int k  = kn >> 8;
    int n  = kn & 255;
    const float* w = (l == 0) ? w1 : (l == 1) ? w2 : w3;
    __half o = __float2half_rn(w[k * 256 + n]);
    int ks = k >> 4, kk = k & 15;
    int nt = n >> 3, c = n & 7;
    int lane = c * 4 + ((kk >> 1) & 3);
    int reg  = kk >> 3;
    int half = kk & 1;
    // ks*8192 = (chunk of 2 ksteps)*16384 + (ks&1)*8192 — same bytes as before
    size_t byte = (size_t)l * 131072 + (size_t)ks * 8192
                + (nt >> 3) * 2048 + (nt & 7) * 256
                + lane * 8 + reg * 4 + half * 2;
    g_wb[byte >> 1] = o;
}

// ---------------- kernel 1: z = conv3x3(feat, W0) + b0 (unchanged) ----------------
__device__ __forceinline__ void prefetch12(uint32_t ws_s, const float* wbase, int ch, int tid) {
    const float* g = wbase + (size_t)ch * 3072;
    uint32_t d = ws_s + (uint32_t)((ch % 3) * 12288);
#pragma unroll
    for (int m = 0; m < 3; ++m) {
        int i4 = tid + 256 * m;
        cpa16(d + i4 * 16, g + i4 * 4);
    }
    cpa_commit();
}

__global__ __launch_bounds__(256, 2) void conv_kernel(
    const float* __restrict__ feat, const float* __restrict__ w0,
    const float* __restrict__ b0)
{
    extern __shared__ float sm[];
    float* fs = sm;            // 64 ch x (10x10) patch
    float* ws = sm + 6400;     // 3 x 3072 weight buffers

    int tid = threadIdx.x;
    int blk = blockIdx.x;
    int bb  = blk >> 8;
    int rem = blk & 255;
    int by = rem >> 4, bx = rem & 15;
    int y0 = by * 8 - 1, x0 = bx * 8 - 1;

    uint32_t ws_s = s2u(ws);
    prefetch12(ws_s, w0, 0, tid);
    prefetch12(ws_s, w0, 1, tid);

    for (int idx = tid; idx < 6400; idx += 256) {
        int c  = idx / 100;
        int p  = idx - c * 100;
        int pr = p / 10;
        int pi = pr + y0;
        int pj = (p - pr * 10) + x0;
        float v = 0.f;
        if ((unsigned)pi < Hh && (unsigned)pj < Ww)
            v = feat[((size_t)(bb * Cch + c) * Hh + pi) * Ww + pj];
        fs[idx] = v;
    }

    int r  = tid >> 5;
    int tx = tid & 31;

    unsigned long long acc[8][4];
#pragma unroll
    for (int i = 0; i < 8; ++i)
#pragma unroll
        for (int j = 0; j < 4; ++j) acc[i][j] = 0ull;

    int c_ = 0, ki = 0;
#pragma unroll 1
    for (int ch = 0; ch < 48; ++ch) {
        if (ch + 1 < 48) cpa_wait1(); else cpa_wait0();
        __syncthreads();
        if (ch + 2 < 48) prefetch12(ws_s, w0, ch + 2, tid);
        const float* wsb = ws + (ch % 3) * 3072;
#pragma unroll
        for (int g = 0; g < 4; ++g) {
            const float* ab = fs + c_ * 100 + (r + ki) * 10;
            unsigned long long a2row[10];
#pragma unroll
            for (int t2 = 0; t2 < 10; ++t2) { float a = ab[t2]; a2row[t2] = pack2(a, a); }
#pragma unroll
            for (int kj = 0; kj < 3; ++kj) {
#pragma unroll
                for (int j = 0; j < 4; ++j) {
                    unsigned long long w2 =
                        *(const unsigned long long*)(wsb + (g * 3 + kj) * 256 + 2 * (tx + 32 * j));
#pragma unroll
                    for (int i = 0; i < 8; ++i)
                        acc[i][j] = fma2(a2row[kj + i], w2, acc[i][j]);
                }
            }
            if (++ki == 3) { ki = 0; ++c_; }
        }
    }

    int gy = by * 8 + r;
#pragma unroll
    for (int j = 0; j < 4; ++j) {
        float2 bb2 = ((const float2*)b0)[tx + 32 * j];
#pragma unroll
        for (int i = 0; i < 8; ++i) {
            float2 v = unpack2(acc[i][j]);
            v.x += bb2.x; v.y += bb2.y;
            int gx = bx * 8 + i;
            *(float2*)(g_z + ((size_t)(bb * Hh + gy) * Ww + gx) * HID + 2 * tx + 64 * j) = v;
        }
    }
}

// ---------------- kernel 2: HMMA MLP (weights via direct LDG) ----------------
// grid = 4096, block = 512 (16 warps, 4x4). CTA: 128 rows x 256 cols, K=256.
// STRUCTURE RULE: straight-line per-layer blocks, unbranched epilogues.
// A region doubles as fp32 scratch 128x260 (133120 B) — sized for the max.
#define OFF_ASH  0
#define OFF_BSM  133120     // b1,b2,b3: 768 f32
#define OFF_W4   136192     // w4: 768 f32
#define OFF_B4   139264     // b4: 4 f32
#define OFF_CW   139280     // W0 rows 576..579: 1024 f32
#define SMEM_TOT 143376

__global__ __launch_bounds__(512, 1) void mlp_mma_kernel(
    const float* __restrict__ coord, const float* __restrict__ cell,
    const float* __restrict__ w0,
    const float* __restrict__ b1, const float* __restrict__ b2,
    const float* __restrict__ b3,
    const float* __restrict__ w4, const float* __restrict__ b4,
    float* __restrict__ out)
{
    extern __shared__ char smc[];
    float* bsm = (float*)(smc + OFF_BSM);
    float* w4s = (float*)(smc + OFF_W4);
    float* b4s = (float*)(smc + OFF_B4);
    float* cw  = (float*)(smc + OFF_CW);

    int tid  = threadIdx.x;
    int lane = tid & 31;
    int wid  = tid >> 5;
    int wm   = wid >> 2;    // rows wm*32..+31
    int wn   = wid & 3;     // cols wn*64..+63

    uint32_t smem_base = s2u(smc);

    for (int i = tid; i < 1024; i += 512) cw[i] = w0[576 * 256 + i];
    for (int i = tid; i < 256; i += 512) {
        bsm[i] = b1[i]; bsm[256 + i] = b2[i]; bsm[512 + i] = b3[i];
    }
    for (int i = tid; i < 768; i += 512) w4s[i] = w4[i];
    if (tid < 3) b4s[tid] = b4[tid];

    // ---- geometry: 4 threads per row ----
    int row  = tid >> 2;
    int part = tid & 3;
    int R  = blockIdx.x * 128 + row;
    int gq = R >> 2;
    int s  = R & 3;
    int b  = gq >> 16;

    float c0  = coord[(size_t)gq * 2 + 0];
    float c1  = coord[(size_t)gq * 2 + 1];
    float ce0 = cell[(size_t)gq * 2 + 0] * 128.0f;
    float ce1 = cell[(size_t)gq * 2 + 1] * 128.0f;
    float vx = (s & 2) ? 1.0f : -1.0f;
    float vy = (s & 1) ? 1.0f : -1.0f;

    const float RXY = 1.0f / 128.0f;
    const float LIM = 1.0f - 1e-6f;
    float cx = c0 + vx * RXY; cx = __fadd_rn(cx, 1e-6f);
    cx = fminf(fmaxf(cx, -LIM), LIM);
    float cy = c1 + vy * RXY; cy = __fadd_rn(cy, 1e-6f);
    cy = fminf(fmaxf(cy, -LIM), LIM);
    float fx = __fmul_rn(__fmul_rn(__fadd_rn(cx, 1.0f), 128.0f), 0.5f);
    float fy = __fmul_rn(__fmul_rn(__fadd_rn(cy, 1.0f), 128.0f), 0.5f);
    int ix = (int)fminf(fmaxf(floorf(fx), 0.0f), 127.0f);
    int iy = (int)fminf(fmaxf(floorf(fy), 0.0f), 127.0f);
    float qx = -1.0f + (2.0f * (float)ix + 1.0f) * (1.0f / 128.0f);
    float qy = -1.0f + (2.0f * (float)iy + 1.0f) * (1.0f / 128.0f);
    float rel0 = __fmul_rn(__fsub_rn(c0, qx), 128.0f);
    float rel1 = __fmul_rn(__fsub_rn(c1, qy), 128.0f);
    float area = fabsf(rel0 * rel1) + 1e-9f;

    __syncthreads();   // cw ready

    // ---- layer-0 input: gather z + rank-4 correction + relu -> A (fp16) ----
    {
        const float4* zrow = (const float4*)(g_z + ((size_t)((b * Hh + ix) * Ww + iy)) * HID);
        const float4* cwa  = (const float4*)cw;
        char* ph = smc + OFF_ASH + row * 528 + part * 128;
#pragma unroll 4
        for (int m = 0; m < 16; ++m) {
            int c4 = part * 16 + m;
            float4 z  = zrow[c4];
            float4 a0 = cwa[c4];
            float4 a1 = cwa[64 + c4];
            float4 a2 = cwa[128 + c4];
            float4 a3 = cwa[192 + c4];
            float v0 = fmaxf(z.x + rel0 * a0.x + rel1 * a1.x + ce0 * a2.x + ce1 * a3.x, 0.f);
            float v1 = fmaxf(z.y + rel0 * a0.y + rel1 * a1.y + ce0 * a2.y + ce1 * a3.y, 0.f);
            float v2 = fmaxf(z.z + rel0 * a0.z + rel1 * a1.z + ce0 * a2.z + ce1 * a3.z, 0.f);
            float v3 = fmaxf(z.w + rel0 * a0.w + rel1 * a1.w + ce0 * a2.w + ce1 * a3.w, 0.f);
            __half2 hp0 = __floats2half2_rn(v0, v1);
            __half2 hp1 = __floats2half2_rn(v2, v3);
            ((uint32_t*)(ph + m * 8))[0] = *reinterpret_cast<uint32_t*>(&hp0);
            ((uint32_t*)(ph + m * 8))[1] = *reinterpret_cast<uint32_t*>(&hp1);
        }
    }
    __syncthreads();   // A ready for layer 0

    // ---- ldmatrix lane base addresses; per-warp weight pointer ----
    int arow = (lane & 7) + ((lane >> 3) & 1) * 8;
    int acol = (lane >> 4) * 16;
    uint32_t ahi0 = smem_base + OFF_ASH + (uint32_t)((wm * 32 + arow) * 528 + acol);
    uint32_t ahi1 = ahi0 + 16 * 528;
    const char* wp0 = (const char*)g_wb + wn * 2048 + lane * 8;

    // ================= layer 0 =================
    {
        const char* wp = wp0;
        float acc[2][8][4];
#pragma unroll
        for (int mt = 0; mt < 2; ++mt)
#pragma unroll
            for (int nt = 0; nt < 8; ++nt)
#pragma unroll
                for (int i = 0; i < 4; ++i) acc[mt][nt][i] = 0.f;

        uint2 Bc[8];
#pragma unroll
        for (int nt = 0; nt < 8; ++nt)
            Bc[nt] = *(const uint2*)(wp + nt * 256);
#pragma unroll
        for (int ks = 0; ks < 16; ++ks) {
            uint2 Bn[8];
            if (ks < 15) {
#pragma unroll
                for (int nt = 0; nt < 8; ++nt)
                    Bn[nt] = *(const uint2*)(wp + (ks + 1) * 8192 + nt * 256);
            }
            uint32_t ah0, ah1, ah2, ah3, ag0, ag1, ag2, ag3;
            ldmA(ah0, ah1, ah2, ah3, ahi0 + ks * 32);
            ldmA(ag0, ag1, ag2, ag3, ahi1 + ks * 32);
#pragma unroll
            for (int nt = 0; nt < 8; ++nt) {
                mma16816(acc[0][nt][0], acc[0][nt][1], acc[0][nt][2], acc[0][nt][3],
                         ah0, ah1, ah2, ah3, Bc[nt].x, Bc[nt].y);
                mma16816(acc[1][nt][0], acc[1][nt][1], acc[1][nt][2], acc[1][nt][3],
                         ag0, ag1, ag2, ag3, Bc[nt].x, Bc[nt].y);
            }
            if (ks < 15) {
#pragma unroll
                for (int nt = 0; nt < 8; ++nt) Bc[nt] = Bn[nt];
            }
        }
        __syncthreads();   // all warps done reading A

        // epilogue: relu(acc + b1) -> fp16
#pragma unroll
        for (int mt = 0; mt < 2; ++mt) {
            int r0 = wm * 32 + mt * 16 + (lane >> 2);
#pragma unroll
            for (int nt = 0; nt < 8; ++nt) {
                int c = wn * 64 + nt * 8 + (lane & 3) * 2;
                float bb0 = bsm[c];
                float bb1 = bsm[c + 1];
#pragma unroll
                for (int hh = 0; hh < 2; ++hh) {
                    int r = r0 + hh * 8;
                    float v0 = fmaxf(acc[mt][nt][2 * hh]     + bb0, 0.f);
                    float v1 = fmaxf(acc[mt][nt][2 * hh + 1] + bb1, 0.f);
                    __half2 hp = __floats2half2_rn(v0, v1);
                    *(uint32_t*)(smc + OFF_ASH + r * 528 + c * 2) =
                        *reinterpret_cast<uint32_t*>(&hp);
                }
            }
        }
        __syncthreads();
    }

    // ================= layer 1 =================
    {
        const char* wp = wp0 + 131072;
        float acc[2][8][4];
#pragma unroll
        for (int mt = 0; mt < 2; ++mt)
#pragma unroll
            for (int nt = 0; nt < 8; ++nt)
#pragma unroll
                for (int i = 0; i < 4; ++i) acc[mt][nt][i] = 0.f;

        uint2 Bc[8];
#pragma unroll
        for (int nt = 0; nt < 8; ++nt)
            Bc[nt] = *(const uint2*)(wp + nt * 256);
#pragma unroll
        for (int ks = 0; ks < 16; ++ks) {
            uint2 Bn[8];
            if (ks < 15) {
#pragma unroll
                for (int nt = 0; nt < 8; ++nt)
                    Bn[nt] = *(const uint2*)(wp + (ks + 1) * 8192 + nt * 256);
            }
            uint32_t ah0, ah1, ah2, ah3, ag0, ag1, ag2, ag3;
            ldmA(ah0, ah1, ah2, ah3, ahi0 + ks * 32);
            ldmA(ag0, ag1, ag2, ag3, ahi1 + ks * 32);
#pragma unroll
            for (int nt = 0; nt < 8; ++nt) {
                mma16816(acc[0][nt][0], acc[0][nt][1], acc[0][nt][2], acc[0][nt][3],
                         ah0, ah1, ah2, ah3, Bc[nt].x, Bc[nt].y);
                mma16816(acc[1][nt][0], acc[1][nt][1], acc[1][nt][2], acc[1][nt][3],
                         ag0, ag1, ag2, ag3, Bc[nt].x, Bc[nt].y);
            }
            if (ks < 15) {
#pragma unroll
                for (int nt = 0; nt < 8; ++nt) Bc[nt] = Bn[nt];
            }
        }
        __syncthreads();

        // epilogue: relu(acc + b2) -> fp16
#pragma unroll
        for (int mt = 0; mt < 2; ++mt) {
            int r0 = wm * 32 + mt * 16 + (lane >> 2);
#pragma unroll
            for (int nt = 0; nt < 8; ++nt) {
                int c = wn * 64 + nt * 8 + (lane & 3) * 2;
                float bb0 = bsm[256 + c];
                float bb1 = bsm[256 + c + 1];
#pragma unroll
                for (int hh = 0; hh < 2; ++hh) {
                    int r = r0 + hh * 8;
                    float v0 = fmaxf(acc[mt][nt][2 * hh]     + bb0, 0.f);
                    float v1 = fmaxf(acc[mt][nt][2 * hh + 1] + bb1, 0.f);
                    __half2 hp = __floats2half2_rn(v0, v1);
                    *(uint32_t*)(smc + OFF_ASH + r * 528 + c * 2) =
                        *reinterpret_cast<uint32_t*>(&hp);
                }
            }
        }
        __syncthreads();
    }

    // ================= layer 2: -> fp32 scratch =================
    {
        const char* wp = wp0 + 262144;
        float acc[2][8][4];
#pragma unroll
        for (int mt = 0; mt < 2; ++mt)
#pragma unroll
            for (int nt = 0; nt < 8; ++nt)
#pragma unroll
                for (int i = 0; i < 4; ++i) acc[mt][nt][i] = 0.f;

        uint2 Bc[8];
#pragma unroll
        for (int nt = 0; nt < 8; ++nt)
            Bc[nt] = *(const uint2*)(wp + nt * 256);
#pragma unroll
        for (int ks = 0; ks < 16; ++ks) {
            uint2 Bn[8];
            if (ks < 15) {
#pragma unroll
                for (int nt = 0; nt < 8; ++nt)
                    Bn[nt] = *(const uint2*)(wp + (ks + 1) * 8192 + nt * 256);
            }
            uint32_t ah0, ah1, ah2, ah3, ag0, ag1, ag2, ag3;
            ldmA(ah0, ah1, ah2, ah3, ahi0 + ks * 32);
            ldmA(ag0, ag1, ag2, ag3, ahi1 + ks * 32);
#pragma unroll
            for (int nt = 0; nt < 8; ++nt) {
                mma16816(acc[0][nt][0], acc[0][nt][1], acc[0][nt][2], acc[0][nt][3],
                         ah0, ah1, ah2, ah3, Bc[nt].x, Bc[nt].y);
                mma16816(acc[1][nt][0], acc[1][nt][1], acc[1][nt][2], acc[1][nt][3],
                         ag0, ag1, ag2, ag3, Bc[nt].x, Bc[nt].y);
            }
            if (ks < 15) {
#pragma unroll
                for (int nt = 0; nt < 8; ++nt) Bc[nt] = Bn[nt];
            }
        }
        __syncthreads();

        // epilogue -> fp32 scratch (133120 B region)
        float* As32 = (float*)(smc + OFF_ASH);
#pragma unroll
        for (int mt = 0; mt < 2; ++mt) {
            int r0 = wm * 32 + mt * 16 + (lane >> 2);
#pragma unroll
            for (int nt = 0; nt < 8; ++nt) {
                int c = wn * 64 + nt * 8 + (lane & 3) * 2;
                float bb0 = bsm[512 + c];
                float bb1 = bsm[512 + c + 1];
#pragma unroll
                for (int hh = 0; hh < 2; ++hh) {
                    int r = r0 + hh * 8;
                    As32[r * 260 + c]     = fmaxf(acc[mt][nt][2 * hh]     + bb0, 0.f);
                    As32[r * 260 + c + 1] = fmaxf(acc[mt][nt][2 * hh + 1] + bb1, 0.f);
                }
            }
        }
        __syncthreads();
    }

    // ---- head + ensemble ----
    {
        const float* As32 = (const float*)(smc + OFF_ASH);
        const float* arow_p = As32 + row * 260 + part * 64;
        float a0 = 0.f, a1 = 0.f, a2 = 0.f;
#pragma unroll 8
        for (int k = 0; k < 64; ++k) {
            float a = arow_p[k];
            int kg = part * 64 + k;
            a0 += a * w4s[kg * 3 + 0];
            a1 += a * w4s[kg * 3 + 1];
            a2 += a * w4s[kg * 3 + 2];
        }
        a0 += __shfl_xor_sync(0xFFFFFFFFu, a0, 1);
        a0 += __shfl_xor_sync(0xFFFFFFFFu, a0, 2);
        a1 += __shfl_xor_sync(0xFFFFFFFFu, a1, 1);
        a1 += __shfl_xor_sync(0xFFFFFFFFu, a1, 2);
        a2 += __shfl_xor_sync(0xFFFFFFFFu, a2, 1);
        a2 += __shfl_xor_sync(0xFFFFFFFFu, a2, 2);
        a0 += b4s[0]; a1 += b4s[1]; a2 += b4s[2];

        float aswap = __shfl_xor_sync(0xFFFFFFFFu, area, 12);
        float t1 = area + __shfl_xor_sync(0xFFFFFFFFu, area, 4);
        float tot = t1 + __shfl_xor_sync(0xFFFFFFFFu, t1, 8);
        float o0 = a0 * aswap, o1 = a1 * aswap, o2 = a2 * aswap;
        o0 += __shfl_xor_sync(0xFFFFFFFFu, o0, 4);
        o0 += __shfl_xor_sync(0xFFFFFFFFu, o0, 8);
        o1 += __shfl_xor_sync(0xFFFFFFFFu, o1, 4);
        o1 += __shfl_xor_sync(0xFFFFFFFFu, o1, 8);
        o2 += __shfl_xor_sync(0xFFFFFFFFu, o2, 4);
        o2 += __shfl_xor_sync(0xFFFFFFFFu, o2, 8);
        if ((tid & 15) == 0) {
            int gqo = blockIdx.x * 32 + (tid >> 4);
            out[(size_t)gqo * 3 + 0] = o0 / tot;
            out[(size_t)gqo * 3 + 1] = o1 / tot;
            out[(size_t)gqo * 3 + 2] = o2 / tot;
        }
    }
}

extern "C" void kernel_launch(void* const* d_in, const int* in_sizes, int n_in,
                              void* d_out, int out_size)
{
    const float* feat  = (const float*)d_in[0];
    const float* coord = (const float*)d_in[1];
    const float* cell  = (const float*)d_in[2];
    const float* w0 = (const float*)d_in[3];
    const float* b0 = (const float*)d_in[4];
    const float* w1 = (const float*)d_in[5];
    const float* b1 = (const float*)d_in[6];
    const float* w2 = (const float*)d_in[7];
    const float* b2 = (const float*)d_in[8];
    const float* w3 = (const float*)d_in[9];
    const float* b3 = (const float*)d_in[10];
    const float* w4 = (const float*)d_in[11];
    const float* b4 = (const float*)d_in[12];
    float* out = (float*)d_out;

    int conv_smem = (6400 + 9216) * 4;
    cudaFuncSetAttribute((const void*)conv_kernel,
                         cudaFuncAttributeMaxDynamicSharedMemorySize, conv_smem);
    cudaFuncSetAttribute((const void*)mlp_mma_kernel,
                         cudaFuncAttributeMaxDynamicSharedMemorySize, SMEM_TOT);

    prep_kernel<<<768, 256>>>(w1, w2, w3);
    conv_kernel<<<512, 256, conv_smem>>>(feat, w0, b0);
    mlp_mma_kernel<<<4096, 512, SMEM_TOT>>>(coord, cell, w0, b1, b2, b3, w4, b4, out);
}

// round 17
// speedup vs baseline: 2.3640x; 1.2124x over previous
#include <cuda_runtime.h>
#include <cuda_fp16.h>
#include <cstdint>

#define Bsz 2
#define Cch 64
#define Hh  128
#define Ww  128
#define HID 256

// 32 MB scratch for conv3x3(feat, W0) + b0, layout [B][H][W][256]
__device__ float g_z[Bsz * Hh * Ww * HID];
// Pre-packed fp16 weights in mma.sync B-fragment layout:
// byte = l*131072 + ks*8192 + (n>>6)*2048 + fragment(lane,reg)  (ks = k>>4)
__device__ __half g_wb[3 * 65536];

// ---------------- generic helpers ----------------
__device__ __forceinline__ unsigned long long pack2(float a, float b) {
    unsigned long long r;
    asm("mov.b64 %0, {%1, %2};" : "=l"(r) : "f"(a), "f"(b));
    return r;
}
__device__ __forceinline__ unsigned long long fma2(unsigned long long a,
                                                   unsigned long long b,
                                                   unsigned long long c) {
    unsigned long long d;
    asm("fma.rn.f32x2 %0, %1, %2, %3;" : "=l"(d) : "l"(a), "l"(b), "l"(c));
    return d;
}
__device__ __forceinline__ float2 unpack2(unsigned long long a) {
    float lo, hi;
    asm("mov.b64 {%0, %1}, %2;" : "=f"(lo), "=f"(hi) : "l"(a));
    return make_float2(lo, hi);
}
__device__ __forceinline__ uint32_t s2u(const void* p) {
    uint32_t a;
    asm("{ .reg .u64 t; cvta.to.shared.u64 t, %1; cvt.u32.u64 %0, t; }" : "=r"(a) : "l"(p));
    return a;
}
__device__ __forceinline__ void cpa16(uint32_t d, const void* s) {
    asm volatile("cp.async.ca.shared.global [%0], [%1], 16;" :: "r"(d), "l"(s));
}
__device__ __forceinline__ void cpa_commit() { asm volatile("cp.async.commit_group;"); }
__device__ __forceinline__ void cpa_wait1()  { asm volatile("cp.async.wait_group 1;"); }
__device__ __forceinline__ void cpa_wait0()  { asm volatile("cp.async.wait_group 0;"); }

__device__ __forceinline__ void ldmA(uint32_t& a0, uint32_t& a1, uint32_t& a2,
                                     uint32_t& a3, uint32_t addr) {
    asm volatile("ldmatrix.sync.aligned.m8n8.x4.shared.b16 {%0,%1,%2,%3}, [%4];"
                 : "=r"(a0), "=r"(a1), "=r"(a2), "=r"(a3) : "r"(addr));
}
__device__ __forceinline__ void mma16816(float& d0, float& d1, float& d2, float& d3,
                                         uint32_t a0, uint32_t a1, uint32_t a2, uint32_t a3,
                                         uint32_t b0, uint32_t b1) {
    asm volatile("mma.sync.aligned.m16n8k16.row.col.f32.f16.f16.f32 "
                 "{%0,%1,%2,%3}, {%4,%5,%6,%7}, {%8,%9}, {%0,%1,%2,%3};"
                 : "+f"(d0), "+f"(d1), "+f"(d2), "+f"(d3)
                 : "r"(a0), "r"(a1), "r"(a2), "r"(a3), "r"(b0), "r"(b1));
}

// ---------------- kernel 0: weight -> fp16 B-fragment layout ----------------
__global__ void prep_kernel(const float* __restrict__ w1,
                            const float* __restrict__ w2,
                            const float* __restrict__ w3)
{
    int t = blockIdx.x * 256 + threadIdx.x;
    if (t >= 3 * 65536) return;
    int l  = t >> 16;
    int kn = t & 65535;
    int k  = kn >> 8;
    int n  = kn & 255;
    const float* w = (l == 0) ? w1 : (l == 1) ? w2 : w3;
    __half o = __float2half_rn(w[k * 256 + n]);
    int ks = k >> 4, kk = k & 15;
    int nt = n >> 3, c = n & 7;
    int lane = c * 4 + ((kk >> 1) & 3);
    int reg  = kk >> 3;
    int half = kk & 1;
    size_t byte = (size_t)l * 131072 + (size_t)ks * 8192
                + (nt >> 3) * 2048 + (nt & 7) * 256
                + lane * 8 + reg * 4 + half * 2;
    g_wb[byte >> 1] = o;
}

// ---------------- kernel 1: z = conv3x3(feat, W0) + b0 (unchanged) ----------------
__device__ __forceinline__ void prefetch12(uint32_t ws_s, const float* wbase, int ch, int tid) {
    const float* g = wbase + (size_t)ch * 3072;
    uint32_t d = ws_s + (uint32_t)((ch % 3) * 12288);
#pragma unroll
    for (int m = 0; m < 3; ++m) {
        int i4 = tid + 256 * m;
        cpa16(d + i4 * 16, g + i4 * 4);
    }
    cpa_commit();
}

__global__ __launch_bounds__(256, 2) void conv_kernel(
    const float* __restrict__ feat, const float* __restrict__ w0,
    const float* __restrict__ b0)
{
    extern __shared__ float sm[];
    float* fs = sm;            // 64 ch x (10x10) patch
    float* ws = sm + 6400;     // 3 x 3072 weight buffers

    int tid = threadIdx.x;
    int blk = blockIdx.x;
    int bb  = blk >> 8;
    int rem = blk & 255;
    int by = rem >> 4, bx = rem & 15;
    int y0 = by * 8 - 1, x0 = bx * 8 - 1;

    uint32_t ws_s = s2u(ws);
    prefetch12(ws_s, w0, 0, tid);
    prefetch12(ws_s, w0, 1, tid);

    for (int idx = tid; idx < 6400; idx += 256) {
        int c  = idx / 100;
        int p  = idx - c * 100;
        int pr = p / 10;
        int pi = pr + y0;
        int pj = (p - pr * 10) + x0;
        float v = 0.f;
        if ((unsigned)pi < Hh && (unsigned)pj < Ww)
            v = feat[((size_t)(bb * Cch + c) * Hh + pi) * Ww + pj];
        fs[idx] = v;
    }

    int r  = tid >> 5;
    int tx = tid & 31;

    unsigned long long acc[8][4];
#pragma unroll
    for (int i = 0; i < 8; ++i)
#pragma unroll
        for (int j = 0; j < 4; ++j) acc[i][j] = 0ull;

    int c_ = 0, ki = 0;
#pragma unroll 1
    for (int ch = 0; ch < 48; ++ch) {
        if (ch + 1 < 48) cpa_wait1(); else cpa_wait0();
        __syncthreads();
        if (ch + 2 < 48) prefetch12(ws_s, w0, ch + 2, tid);
        const float* wsb = ws + (ch % 3) * 3072;
#pragma unroll
        for (int g = 0; g < 4; ++g) {
            const float* ab = fs + c_ * 100 + (r + ki) * 10;
            unsigned long long a2row[10];
#pragma unroll
            for (int t2 = 0; t2 < 10; ++t2) { float a = ab[t2]; a2row[t2] = pack2(a, a); }
#pragma unroll
            for (int kj = 0; kj < 3; ++kj) {
#pragma unroll
                for (int j = 0; j < 4; ++j) {
                    unsigned long long w2 =
                        *(const unsigned long long*)(wsb + (g * 3 + kj) * 256 + 2 * (tx + 32 * j));
#pragma unroll
                    for (int i = 0; i < 8; ++i)
                        acc[i][j] = fma2(a2row[kj + i], w2, acc[i][j]);
                }
            }
            if (++ki == 3) { ki = 0; ++c_; }
        }
    }

    int gy = by * 8 + r;
#pragma unroll
    for (int j = 0; j < 4; ++j) {
        float2 bb2 = ((const float2*)b0)[tx + 32 * j];
#pragma unroll
        for (int i = 0; i < 8; ++i) {
            float2 v = unpack2(acc[i][j]);
            v.x += bb2.x; v.y += bb2.y;
            int gx = bx * 8 + i;
            *(float2*)(g_z + ((size_t)(bb * Hh + gy) * Ww + gx) * HID + 2 * tx + 64 * j) = v;
        }
    }
}

// ---------------- kernel 2: HMMA MLP (direct-LDG weights, fused head) ----------------
// grid = 4096, block = 512 (16 warps, 4x4). CTA: 128 rows x 256 cols, K=256.
// STRUCTURE RULE: straight-line per-layer blocks, unbranched epilogues.
#define OFF_ASH  0          // A fp16: 128 x 528 B (67584)
#define OFF_BSM  67584      // b1,b2,b3: 768 f32
#define OFF_W4   70656      // w4: 768 f32
#define OFF_B4   73728      // b4: 4 f32
#define OFF_CW   73744      // W0 rows 576..579: 1024 f32
#define OFF_PRED 77840      // preds: 128 x 4 x 3 f32 (6144)
#define OFF_AREA 83984      // areas: 128 f32
#define SMEM_TOT 84496

__global__ __launch_bounds__(512, 1) void mlp_mma_kernel(
    const float* __restrict__ coord, const float* __restrict__ cell,
    const float* __restrict__ w0,
    const float* __restrict__ b1, const float* __restrict__ b2,
    const float* __restrict__ b3,
    const float* __restrict__ w4, const float* __restrict__ b4,
    float* __restrict__ out)
{
    extern __shared__ char smc[];
    float* bsm   = (float*)(smc + OFF_BSM);
    float* w4s   = (float*)(smc + OFF_W4);
    float* b4s   = (float*)(smc + OFF_B4);
    float* cw    = (float*)(smc + OFF_CW);
    float* preds = (float*)(smc + OFF_PRED);
    float* areas = (float*)(smc + OFF_AREA);

    int tid  = threadIdx.x;
    int lane = tid & 31;
    int wid  = tid >> 5;
    int wm   = wid >> 2;    // rows wm*32..+31
    int wn   = wid & 3;     // cols wn*64..+63

    uint32_t smem_base = s2u(smc);

    for (int i = tid; i < 1024; i += 512) cw[i] = w0[576 * 256 + i];
    for (int i = tid; i < 256; i += 512) {
        bsm[i] = b1[i]; bsm[256 + i] = b2[i]; bsm[512 + i] = b3[i];
    }
    for (int i = tid; i < 768; i += 512) w4s[i] = w4[i];
    if (tid < 3) b4s[tid] = b4[tid];

    // ---- geometry: 4 threads per row ----
    int row  = tid >> 2;
    int part = tid & 3;
    int R  = blockIdx.x * 128 + row;
    int gq = R >> 2;
    int s  = R & 3;
    int b  = gq >> 16;

    float c0  = coord[(size_t)gq * 2 + 0];
    float c1  = coord[(size_t)gq * 2 + 1];
    float ce0 = cell[(size_t)gq * 2 + 0] * 128.0f;
    float ce1 = cell[(size_t)gq * 2 + 1] * 128.0f;
    float vx = (s & 2) ? 1.0f : -1.0f;
    float vy = (s & 1) ? 1.0f : -1.0f;

    const float RXY = 1.0f / 128.0f;
    const float LIM = 1.0f - 1e-6f;
    float cx = c0 + vx * RXY; cx = __fadd_rn(cx, 1e-6f);
    cx = fminf(fmaxf(cx, -LIM), LIM);
    float cy = c1 + vy * RXY; cy = __fadd_rn(cy, 1e-6f);
    cy = fminf(fmaxf(cy, -LIM), LIM);
    float fx = __fmul_rn(__fmul_rn(__fadd_rn(cx, 1.0f), 128.0f), 0.5f);
    float fy = __fmul_rn(__fmul_rn(__fadd_rn(cy, 1.0f), 128.0f), 0.5f);
    int ix = (int)fminf(fmaxf(floorf(fx), 0.0f), 127.0f);
    int iy = (int)fminf(fmaxf(floorf(fy), 0.0f), 127.0f);
    float qx = -1.0f + (2.0f * (float)ix + 1.0f) * (1.0f / 128.0f);
    float qy = -1.0f + (2.0f * (float)iy + 1.0f) * (1.0f / 128.0f);
    float rel0 = __fmul_rn(__fsub_rn(c0, qx), 128.0f);
    float rel1 = __fmul_rn(__fsub_rn(c1, qy), 128.0f);
    if (part == 0) areas[row] = fabsf(rel0 * rel1) + 1e-9f;

    __syncthreads();   // cw ready

    // ---- layer-0 input: gather z + rank-4 correction + relu -> A (fp16) ----
    {
        const float4* zrow = (const float4*)(g_z + ((size_t)((b * Hh + ix) * Ww + iy)) * HID);
        const float4* cwa  = (const float4*)cw;
        char* ph = smc + OFF_ASH + row * 528 + part * 128;
#pragma unroll 4
        for (int m = 0; m < 16; ++m) {
            int c4 = part * 16 + m;
            float4 z  = zrow[c4];
            float4 a0 = cwa[c4];
            float4 a1 = cwa[64 + c4];
            float4 a2 = cwa[128 + c4];
            float4 a3 = cwa[192 + c4];
            float v0 = fmaxf(z.x + rel0 * a0.x + rel1 * a1.x + ce0 * a2.x + ce1 * a3.x, 0.f);
            float v1 = fmaxf(z.y + rel0 * a0.y + rel1 * a1.y + ce0 * a2.y + ce1 * a3.y, 0.f);
            float v2 = fmaxf(z.z + rel0 * a0.z + rel1 * a1.z + ce0 * a2.z + ce1 * a3.z, 0.f);
            float v3 = fmaxf(z.w + rel0 * a0.w + rel1 * a1.w + ce0 * a2.w + ce1 * a3.w, 0.f);
            __half2 hp0 = __floats2half2_rn(v0, v1);
            __half2 hp1 = __floats2half2_rn(v2, v3);
            ((uint32_t*)(ph + m * 8))[0] = *reinterpret_cast<uint32_t*>(&hp0);
            ((uint32_t*)(ph + m * 8))[1] = *reinterpret_cast<uint32_t*>(&hp1);
        }
    }
    __syncthreads();   // A ready for layer 0

    // ---- ldmatrix lane base addresses; per-warp weight pointer ----
    int arow = (lane & 7) + ((lane >> 3) & 1) * 8;
    int acol = (lane >> 4) * 16;
    uint32_t ahi0 = smem_base + OFF_ASH + (uint32_t)((wm * 32 + arow) * 528 + acol);
    uint32_t ahi1 = ahi0 + 16 * 528;
    const char* wp0 = (const char*)g_wb + wn * 2048 + lane * 8;

    // ================= layer 0 =================
    {
        const char* wp = wp0;
        float acc[2][8][4];
#pragma unroll
        for (int mt = 0; mt < 2; ++mt)
#pragma unroll
            for (int nt = 0; nt < 8; ++nt)
#pragma unroll
                for (int i = 0; i < 4; ++i) acc[mt][nt][i] = 0.f;

        uint2 Bc[8];
#pragma unroll
        for (int nt = 0; nt < 8; ++nt)
            Bc[nt] = *(const uint2*)(wp + nt * 256);
#pragma unroll
        for (int ks = 0; ks < 16; ++ks) {
            uint2 Bn[8];
            if (ks < 15) {
#pragma unroll
                for (int nt = 0; nt < 8; ++nt)
                    Bn[nt] = *(const uint2*)(wp + (ks + 1) * 8192 + nt * 256);
            }
            uint32_t ah0, ah1, ah2, ah3, ag0, ag1, ag2, ag3;
            ldmA(ah0, ah1, ah2, ah3, ahi0 + ks * 32);
            ldmA(ag0, ag1, ag2, ag3, ahi1 + ks * 32);
#pragma unroll
            for (int nt = 0; nt < 8; ++nt) {
                mma16816(acc[0][nt][0], acc[0][nt][1], acc[0][nt][2], acc[0][nt][3],
                         ah0, ah1, ah2, ah3, Bc[nt].x, Bc[nt].y);
                mma16816(acc[1][nt][0], acc[1][nt][1], acc[1][nt][2], acc[1][nt][3],
                         ag0, ag1, ag2, ag3, Bc[nt].x, Bc[nt].y);
            }
            if (ks < 15) {
#pragma unroll
                for (int nt = 0; nt < 8; ++nt) Bc[nt] = Bn[nt];
            }
        }
        __syncthreads();   // all warps done reading A

        // epilogue: relu(acc + b1) -> fp16
#pragma unroll
        for (int mt = 0; mt < 2; ++mt) {
            int r0 = wm * 32 + mt * 16 + (lane >> 2);
#pragma unroll
            for (int nt = 0; nt < 8; ++nt) {
                int c = wn * 64 + nt * 8 + (lane & 3) * 2;
                float bb0 = bsm[c];
                float bb1 = bsm[c + 1];
#pragma unroll
                for (int hh = 0; hh < 2; ++hh) {
                    int r = r0 + hh * 8;
                    float v0 = fmaxf(acc[mt][nt][2 * hh]     + bb0, 0.f);
                    float v1 = fmaxf(acc[mt][nt][2 * hh + 1] + bb1, 0.f);
                    __half2 hp = __floats2half2_rn(v0, v1);
                    *(uint32_t*)(smc + OFF_ASH + r * 528 + c * 2) =
                        *reinterpret_cast<uint32_t*>(&hp);
                }
            }
        }
        __syncthreads();
    }

    // ================= layer 1 =================
    {
        const char* wp = wp0 + 131072;
        float acc[2][8][4];
#pragma unroll
        for (int mt = 0; mt < 2; ++mt)
#pragma unroll
            for (int nt = 0; nt < 8; ++nt)
#pragma unroll
                for (int i = 0; i < 4; ++i) acc[mt][nt][i] = 0.f;

        uint2 Bc[8];
#pragma unroll
        for (int nt = 0; nt < 8; ++nt)
            Bc[nt] = *(const uint2*)(wp + nt * 256);
#pragma unroll
        for (int ks = 0; ks < 16; ++ks) {
            uint2 Bn[8];
            if (ks < 15) {
#pragma unroll
                for (int nt = 0; nt < 8; ++nt)
                    Bn[nt] = *(const uint2*)(wp + (ks + 1) * 8192 + nt * 256);
            }
            uint32_t ah0, ah1, ah2, ah3, ag0, ag1, ag2, ag3;
            ldmA(ah0, ah1, ah2, ah3, ahi0 + ks * 32);
            ldmA(ag0, ag1, ag2, ag3, ahi1 + ks * 32);
#pragma unroll
            for (int nt = 0; nt < 8; ++nt) {
                mma16816(acc[0][nt][0], acc[0][nt][1], acc[0][nt][2], acc[0][nt][3],
                         ah0, ah1, ah2, ah3, Bc[nt].x, Bc[nt].y);
                mma16816(acc[1][nt][0], acc[1][nt][1], acc[1][nt][2], acc[1][nt][3],
                         ag0, ag1, ag2, ag3, Bc[nt].x, Bc[nt].y);
            }
            if (ks < 15) {
#pragma unroll
                for (int nt = 0; nt < 8; ++nt) Bc[nt] = Bn[nt];
            }
        }
        __syncthreads();

        // epilogue: relu(acc + b2) -> fp16
#pragma unroll
        for (int mt = 0; mt < 2; ++mt) {
            int r0 = wm * 32 + mt * 16 + (lane >> 2);
#pragma unroll
            for (int nt = 0; nt < 8; ++nt) {
                int c = wn * 64 + nt * 8 + (lane & 3) * 2;
                float bb0 = bsm[256 + c];
                float bb1 = bsm[256 + c + 1];
#pragma unroll
                for (int hh = 0; hh < 2; ++hh) {
                    int r = r0 + hh * 8;
                    float v0 = fmaxf(acc[mt][nt][2 * hh]     + bb0, 0.f);
                    float v1 = fmaxf(acc[mt][nt][2 * hh + 1] + bb1, 0.f);
                    __half2 hp = __floats2half2_rn(v0, v1);
                    *(uint32_t*)(smc + OFF_ASH + r * 528 + c * 2) =
                        *reinterpret_cast<uint32_t*>(&hp);
                }
            }
        }
        __syncthreads();
    }

    // ================= layer 2: fused head epilogue =================
    {
        const char* wp = wp0 + 262144;
        float acc[2][8][4];
#pragma unroll
        for (int mt = 0; mt < 2; ++mt)
#pragma unroll
            for (int nt = 0; nt < 8; ++nt)
#pragma unroll
                for (int i = 0; i < 4; ++i) acc[mt][nt][i] = 0.f;

        uint2 Bc[8];
#pragma unroll
        for (int nt = 0; nt < 8; ++nt)
            Bc[nt] = *(const uint2*)(wp + nt * 256);
#pragma unroll
        for (int ks = 0; ks < 16; ++ks) {
            uint2 Bn[8];
            if (ks < 15) {
#pragma unroll
                for (int nt = 0; nt < 8; ++nt)
                    Bn[nt] = *(const uint2*)(wp + (ks + 1) * 8192 + nt * 256);
            }
            uint32_t ah0, ah1, ah2, ah3, ag0, ag1, ag2, ag3;
            ldmA(ah0, ah1, ah2, ah3, ahi0 + ks * 32);
            ldmA(ag0, ag1, ag2, ag3, ahi1 + ks * 32);
#pragma unroll
            for (int nt = 0; nt < 8; ++nt) {
                mma16816(acc[0][nt][0], acc[0][nt][1], acc[0][nt][2], acc[0][nt][3],
                         ah0, ah1, ah2, ah3, Bc[nt].x, Bc[nt].y);
                mma16816(acc[1][nt][0], acc[1][nt][1], acc[1][nt][2], acc[1][nt][3],
                         ag0, ag1, ag2, ag3, Bc[nt].x, Bc[nt].y);
            }
            if (ks < 15) {
#pragma unroll
                for (int nt = 0; nt < 8; ++nt) Bc[nt] = Bn[nt];
            }
        }
        // no A-protect sync needed: nothing writes the A region after this

        // fused head: p[mt][hh][d] = sum over this thread's 16 cols
        float p[2][2][3];
#pragma unroll
        for (int mt = 0; mt < 2; ++mt)
#pragma unroll
            for (int hh = 0; hh < 2; ++hh)
#pragma unroll
                for (int d = 0; d < 3; ++d) p[mt][hh][d] = 0.f;
#pragma unroll
        for (int nt = 0; nt < 8; ++nt) {
            int c = wn * 64 + nt * 8 + (lane & 3) * 2;
            float bb0 = bsm[512 + c];
            float bb1 = bsm[512 + c + 1];
            float w40 = w4s[c * 3 + 0], w41 = w4s[c * 3 + 1], w42 = w4s[c * 3 + 2];
            float w50 = w4s[c * 3 + 3], w51 = w4s[c * 3 + 4], w52 = w4s[c * 3 + 5];
#pragma unroll
            for (int mt = 0; mt < 2; ++mt)
#pragma unroll
                for (int hh = 0; hh < 2; ++hh) {
                    float v0 = fmaxf(acc[mt][nt][2 * hh]     + bb0, 0.f);
                    float v1 = fmaxf(acc[mt][nt][2 * hh + 1] + bb1, 0.f);
                    p[mt][hh][0] += v0 * w40 + v1 * w50;
                    p[mt][hh][1] += v0 * w41 + v1 * w51;
                    p[mt][hh][2] += v0 * w42 + v1 * w52;
                }
        }
        // reduce across the 4 col-lanes (lane&3)
#pragma unroll
        for (int mt = 0; mt < 2; ++mt)
#pragma unroll
            for (int hh = 0; hh < 2; ++hh)
#pragma unroll
                for (int d = 0; d < 3; ++d) {
                    p[mt][hh][d] += __shfl_xor_sync(0xFFFFFFFFu, p[mt][hh][d], 1);
                    p[mt][hh][d] += __shfl_xor_sync(0xFFFFFFFFu, p[mt][hh][d], 2);
                }
        if ((lane & 3) == 0) {
            int rb = wm * 32 + (lane >> 2);
#pragma unroll
            for (int mt = 0; mt < 2; ++mt)
#pragma unroll
                for (int hh = 0; hh < 2; ++hh) {
                    int r = rb + mt * 16 + hh * 8;
                    preds[r * 12 + wn * 3 + 0] = p[mt][hh][0];
                    preds[r * 12 + wn * 3 + 1] = p[mt][hh][1];
                    preds[r * 12 + wn * 3 + 2] = p[mt][hh][2];
                }
        }
    }

    // ---- ensemble combine (deterministic: sum 4 wn slots) ----
    __syncthreads();
    if (tid < 32) {
        int g = tid;
        float a0 = areas[4 * g + 0], a1 = areas[4 * g + 1];
        float a2 = areas[4 * g + 2], a3 = areas[4 * g + 3];
        float tot = a0 + a1 + a2 + a3;
        float wg0 = a3 / tot, wg1 = a2 / tot, wg2 = a1 / tot, wg3 = a0 / tot;
        int gqo = blockIdx.x * 32 + g;
#pragma unroll
        for (int d = 0; d < 3; ++d) {
            float bb = b4s[d];
            float s0 = preds[(4 * g + 0) * 12 + d]     + preds[(4 * g + 0) * 12 + 3 + d]
                     + preds[(4 * g + 0) * 12 + 6 + d] + preds[(4 * g + 0) * 12 + 9 + d] + bb;
            float s1 = preds[(4 * g + 1) * 12 + d]     + preds[(4 * g + 1) * 12 + 3 + d]
                     + preds[(4 * g + 1) * 12 + 6 + d] + preds[(4 * g + 1) * 12 + 9 + d] + bb;
            float s2 = preds[(4 * g + 2) * 12 + d]     + preds[(4 * g + 2) * 12 + 3 + d]
                     + preds[(4 * g + 2) * 12 + 6 + d] + preds[(4 * g + 2) * 12 + 9 + d] + bb;
            float s3 = preds[(4 * g + 3) * 12 + d]     + preds[(4 * g + 3) * 12 + 3 + d]
                     + preds[(4 * g + 3) * 12 + 6 + d] + preds[(4 * g + 3) * 12 + 9 + d] + bb;
            out[(size_t)gqo * 3 + d] = s0 * wg0 + s1 * wg1 + s2 * wg2 + s3 * wg3;
        }
    }
}

extern "C" void kernel_launch(void* const* d_in, const int* in_sizes, int n_in,
                              void* d_out, int out_size)
{
    const float* feat  = (const float*)d_in[0];
    const float* coord = (const float*)d_in[1];
    const float* cell  = (const float*)d_in[2];
    const float* w0 = (const float*)d_in[3];
    const float* b0 = (const float*)d_in[4];
    const float* w1 = (const float*)d_in[5];
    const float* b1 = (const float*)d_in[6];
    const float* w2 = (const float*)d_in[7];
    const float* b2 = (const float*)d_in[8];
    const float* w3 = (const float*)d_in[9];
    const float* b3 = (const float*)d_in[10];
    const float* w4 = (const float*)d_in[11];
    const float* b4 = (const float*)d_in[12];
    float* out = (float*)d_out;

    int conv_smem = (6400 + 9216) * 4;
    cudaFuncSetAttribute((const void*)conv_kernel,
                         cudaFuncAttributeMaxDynamicSharedMemorySize, conv_smem);
    cudaFuncSetAttribute((const void*)mlp_mma_kernel,
                         cudaFuncAttributeMaxDynamicSharedMemorySize, SMEM_TOT);

    prep_kernel<<<768, 256>>>(w1, w2, w3);
    conv_kernel<<<512, 256, conv_smem>>>(feat, w0, b0);
    mlp_mma_kernel<<<4096, 512, SMEM_TOT>>>(coord, cell, w0, b1, b2, b3, w4, b4, out);
}